// round 1
// baseline (speedup 1.0000x reference)
#include <cuda_runtime.h>
#include <math.h>

#define Bn  16
#define Dn  192
#define TXn 512
#define TYn 2048
#define NEGV (-1e9f)

// ---- scratch (device globals; no allocation allowed) ----
__device__ __align__(16) float g_nc  [Bn * TYn * TXn];  // 64 MB neg_cent
__device__ __align__(16) float g_bms [Bn * Dn * TXn];   // x_mean * s
__device__ __align__(16) float g_bs  [Bn * Dn * TXn];   // s = exp(-2*x_logs)
__device__ __align__(16) float g_cvec[Bn * TXn];        // nc1 + nc4 per (b,x)
__device__ int   g_path[Bn * TYn];

// ---------------------------------------------------------------------------
// Kernel 1: prep — s, m*s, and the per-x constant vector (nc1+nc4)
// grid (TX/128, B), block 128; one thread owns one (b,x), loops over d.
// ---------------------------------------------------------------------------
__global__ void prep_kernel(const float* __restrict__ xm,
                            const float* __restrict__ xl) {
    int b = blockIdx.y;
    int x = blockIdx.x * 128 + threadIdx.x;
    const float* xmb = xm + b * Dn * TXn;
    const float* xlb = xl + b * Dn * TXn;
    float* bms = g_bms + b * Dn * TXn;
    float* bs  = g_bs  + b * Dn * TXn;
    float c = 0.0f;
    #pragma unroll 4
    for (int d = 0; d < Dn; d++) {
        float m = xmb[d * TXn + x];
        float l = xlb[d * TXn + x];
        float s = expf(-2.0f * l);
        bs [d * TXn + x] = s;
        bms[d * TXn + x] = m * s;
        c += (-l) + (-0.5f * m * m * s);
    }
    // nc1 constant term: -D * 0.5*log(2*pi)
    g_cvec[b * TXn + x] = c - (float)Dn * 0.91893853320467274f;
}

// ---------------------------------------------------------------------------
// Kernel 2: nc GEMM.  nc[b,y,x] = sum_d z[d,y]*bms[d,x] + (-0.5 z^2)[d,y]*bs[d,x] + cvec[x]
// Tile 128(y) x 128(x), K-chunk 8, 256 threads, 8x8 per-thread microtile.
// Skips tiles fully above the diagonal (masked later) and fully below the
// reachable band (never read by backtrack nor feeding band values).
// ---------------------------------------------------------------------------
__global__ __launch_bounds__(256) void nc_gemm_kernel(const float* __restrict__ z) {
    int bx = blockIdx.x;   // x tile 0..3
    int by = blockIdx.y;   // y tile 0..15
    int b  = blockIdx.z;
    if (bx > by) return;            // whole tile has x > y (masked to NEG by MAS)
    if (bx <= by - 13) return;      // whole tile strictly below reachable band

    __shared__ float s_z [8][128];
    __shared__ float s_z2[8][128];
    __shared__ float s_ms[8][128];
    __shared__ float s_s [8][128];

    int tid = threadIdx.x;
    int lr = tid >> 5;            // 0..7  (k row for loads)
    int lc = (tid & 31) * 4;      // 0..124 (col for loads)
    int ty = tid >> 4;            // 0..15
    int tx = tid & 15;            // 0..15

    const float* zb  = z     + b * Dn * TYn + by * 128;
    const float* msb = g_bms + b * Dn * TXn + bx * 128;
    const float* ssb = g_bs  + b * Dn * TXn + bx * 128;

    float acc[8][8];
    #pragma unroll
    for (int i = 0; i < 8; i++)
        #pragma unroll
        for (int j = 0; j < 8; j++) acc[i][j] = 0.0f;

    for (int d0 = 0; d0 < Dn; d0 += 8) {
        float4 az  = *(const float4*)(zb  + (d0 + lr) * TYn + lc);
        float4 ams = *(const float4*)(msb + (d0 + lr) * TXn + lc);
        float4 ass = *(const float4*)(ssb + (d0 + lr) * TXn + lc);
        __syncthreads();
        *(float4*)&s_z [lr][lc] = az;
        float4 az2 = make_float4(-0.5f * az.x * az.x, -0.5f * az.y * az.y,
                                 -0.5f * az.z * az.z, -0.5f * az.w * az.w);
        *(float4*)&s_z2[lr][lc] = az2;
        *(float4*)&s_ms[lr][lc] = ams;
        *(float4*)&s_s [lr][lc] = ass;
        __syncthreads();

        #pragma unroll
        for (int kk = 0; kk < 8; kk++) {
            float a1[8], a2[8], bm[8], bsv[8];
            *(float4*)&a1[0]  = *(const float4*)&s_z [kk][ty * 8];
            *(float4*)&a1[4]  = *(const float4*)&s_z [kk][ty * 8 + 4];
            *(float4*)&a2[0]  = *(const float4*)&s_z2[kk][ty * 8];
            *(float4*)&a2[4]  = *(const float4*)&s_z2[kk][ty * 8 + 4];
            *(float4*)&bm[0]  = *(const float4*)&s_ms[kk][tx * 8];
            *(float4*)&bm[4]  = *(const float4*)&s_ms[kk][tx * 8 + 4];
            *(float4*)&bsv[0] = *(const float4*)&s_s [kk][tx * 8];
            *(float4*)&bsv[4] = *(const float4*)&s_s [kk][tx * 8 + 4];
            #pragma unroll
            for (int i = 0; i < 8; i++)
                #pragma unroll
                for (int j = 0; j < 8; j++) {
                    acc[i][j] = fmaf(a1[i], bm[j],  acc[i][j]);
                    acc[i][j] = fmaf(a2[i], bsv[j], acc[i][j]);
                }
        }
    }

    float cv[8];
    *(float4*)&cv[0] = *(const float4*)(g_cvec + b * TXn + bx * 128 + tx * 8);
    *(float4*)&cv[4] = *(const float4*)(g_cvec + b * TXn + bx * 128 + tx * 8 + 4);

    float* outp = g_nc + b * TYn * TXn + (by * 128 + ty * 8) * TXn + bx * 128 + tx * 8;
    #pragma unroll
    for (int i = 0; i < 8; i++) {
        float4 o0 = make_float4(acc[i][0] + cv[0], acc[i][1] + cv[1],
                                acc[i][2] + cv[2], acc[i][3] + cv[3]);
        float4 o1 = make_float4(acc[i][4] + cv[4], acc[i][5] + cv[5],
                                acc[i][6] + cv[6], acc[i][7] + cv[7]);
        *(float4*)(outp + i * TXn)     = o0;
        *(float4*)(outp + i * TXn + 4) = o1;
    }
}

// ---------------------------------------------------------------------------
// Kernel 3: MAS — one warp per batch. Forward DP with registers + shfl,
// direction bits in dynamic shared (128KB), backtrack, durations, l_length,
// attn one-hot scatter.
// ---------------------------------------------------------------------------
__global__ void mas_kernel(const float* __restrict__ logw,
                           float* __restrict__ out_llen,
                           float* __restrict__ out_attn) {
    extern __shared__ unsigned short s_dirs[];   // [TYn][32] bit-packed, 128 KB
    __shared__ unsigned short path_sm[TYn];
    __shared__ int w_sm[TXn];

    int b = blockIdx.x;
    int lane = threadIdx.x;
    const float* nc = g_nc + (size_t)b * TYn * TXn;
    int base = lane * 16;

    float v[16];
    #pragma unroll
    for (int i = 0; i < 16; i++) v[i] = NEGV;
    if (lane == 0) v[0] = nc[0];          // v0 = where(x==0, nc[0], NEG)

    // prefetch row 1
    float4 pf0, pf1, pf2, pf3;
    {
        const float4* r = (const float4*)(nc + TXn + base);
        pf0 = r[0]; pf1 = r[1]; pf2 = r[2]; pf3 = r[3];
    }

    for (int y = 1; y < TYn; y++) {
        float cur[16];
        *(float4*)&cur[0]  = pf0;
        *(float4*)&cur[4]  = pf1;
        *(float4*)&cur[8]  = pf2;
        *(float4*)&cur[12] = pf3;
        if (y + 1 < TYn) {
            const float4* r = (const float4*)(nc + (size_t)(y + 1) * TXn + base);
            pf0 = r[0]; pf1 = r[1]; pf2 = r[2]; pf3 = r[3];
        }

        float up  = __shfl_up_sync(0xffffffffu, v[15], 1);
        float vd0 = (lane == 0) ? NEGV : up;

        unsigned int bits = 0u;
        float nv[16];
        bits |= (vd0 > v[0]) ? 1u : 0u;
        nv[0] = cur[0] + fmaxf(v[0], vd0);
        #pragma unroll
        for (int i = 1; i < 16; i++) {
            bits |= (v[i - 1] > v[i]) ? (1u << i) : 0u;
            nv[i] = cur[i] + fmaxf(v[i], v[i - 1]);
        }
        if (y < TXn - 1) {                 // mask x<=y (only matters for y<511)
            #pragma unroll
            for (int i = 0; i < 16; i++)
                if (base + i > y) nv[i] = NEGV;
        }
        #pragma unroll
        for (int i = 0; i < 16; i++) v[i] = nv[i];

        s_dirs[y * 32 + lane] = (unsigned short)bits;
    }
    __syncwarp();

    // backtrack (lane 0), path into shared
    if (lane == 0) {
        int idx = TXn - 1;
        for (int y = TYn - 1; y >= 1; y--) {
            path_sm[y] = (unsigned short)idx;
            unsigned int wbits = s_dirs[y * 32 + (idx >> 4)];
            idx -= (int)((wbits >> (idx & 15)) & 1u);
        }
        path_sm[0] = (unsigned short)idx;
    }
    __syncwarp();

    for (int x = lane; x < TXn; x += 32) w_sm[x] = 0;
    __syncwarp();

    for (int y = lane; y < TYn; y += 32) {
        int px = path_sm[y];
        g_path[b * TYn + y] = px;
        atomicAdd(&w_sm[px], 1);
        out_attn[(size_t)b * TYn * TXn + (size_t)y * TXn + px] = 1.0f;
    }
    __syncwarp();

    float part = 0.0f;
    for (int x = lane; x < TXn; x += 32) {
        float lw = logw[b * TXn + x];
        float d  = lw - logf((float)w_sm[x] + 1e-6f);
        part += d * d;
    }
    #pragma unroll
    for (int o = 16; o > 0; o >>= 1)
        part += __shfl_down_sync(0xffffffffu, part, o);
    if (lane == 0) out_llen[b] = part;
}

// ---------------------------------------------------------------------------
// Kernel 4: gather out_main[b,d,y] = x[b,d,path[b,y]]
// ---------------------------------------------------------------------------
__global__ void gather_kernel(const float* __restrict__ xm,
                              const float* __restrict__ xl,
                              float* __restrict__ out_main) {
    int b = blockIdx.y;
    int y = blockIdx.x * 256 + threadIdx.x;
    int px = g_path[b * TYn + y];
    const float* xmb = xm + b * Dn * TXn + px;
    const float* xlb = xl + b * Dn * TXn + px;
    float* o = out_main + (size_t)b * 2 * Dn * TYn + y;
    #pragma unroll 4
    for (int d = 0; d < Dn; d++)
        o[d * TYn] = xmb[d * TXn];
    #pragma unroll 4
    for (int d = 0; d < Dn; d++)
        o[(Dn + d) * TYn] = xlb[d * TXn];
}

// ---------------------------------------------------------------------------
extern "C" void kernel_launch(void* const* d_in, const int* in_sizes, int n_in,
                              void* d_out, int out_size) {
    const float* xm   = (const float*)d_in[0];  // [B,D,TX]
    const float* xl   = (const float*)d_in[1];  // [B,D,TX]
    const float* z    = (const float*)d_in[2];  // [B,D,TY]
    const float* logw = (const float*)d_in[3];  // [B,1,TX]

    float* out       = (float*)d_out;
    const size_t OM  = (size_t)Bn * 2 * Dn * TYn;      // 12,582,912
    float* out_main  = out;
    float* out_llen  = out + OM;
    float* out_attn  = out + OM + Bn;

    cudaFuncSetAttribute(mas_kernel,
                         cudaFuncAttributeMaxDynamicSharedMemorySize,
                         TYn * 32 * (int)sizeof(unsigned short));

    prep_kernel<<<dim3(TXn / 128, Bn), 128>>>(xm, xl);
    nc_gemm_kernel<<<dim3(TXn / 128, TYn / 128, Bn), 256>>>(z);
    cudaMemsetAsync(out_attn, 0, (size_t)Bn * TYn * TXn * sizeof(float));
    mas_kernel<<<Bn, 32, TYn * 32 * (int)sizeof(unsigned short)>>>(logw, out_llen, out_attn);
    gather_kernel<<<dim3(TYn / 256, Bn), 256>>>(xm, xl, out_main);
}

// round 2
// speedup vs baseline: 1.6249x; 1.6249x over previous
#include <cuda_runtime.h>
#include <math.h>
#include <string.h>

#define Bn  16
#define Dn  192
#define TXn 512
#define TYn 2048
#define NEGV (-1e9f)

// ---- scratch (device globals; no allocation allowed) ----
__device__ __align__(16) float g_nc  [Bn * TYn * TXn];  // 64 MB neg_cent
__device__ __align__(16) float g_bms [Bn * Dn * TXn];   // x_mean * s
__device__ __align__(16) float g_bs  [Bn * Dn * TXn];   // s = exp(-2*x_logs)
__device__ __align__(16) float g_cvec[Bn * TXn];        // nc1 + nc4 per (b,x)
__device__ int   g_path[Bn * TYn];

// packed fp32x2 FMA (Blackwell): d = a*b + d on both 32-bit halves, rn each.
__device__ __forceinline__ void fma2(unsigned long long& d,
                                     unsigned long long a,
                                     unsigned long long b) {
    asm("fma.rn.f32x2 %0, %1, %2, %0;" : "+l"(d) : "l"(a), "l"(b));
}

// ---------------------------------------------------------------------------
// Kernel 1: prep — s, m*s, and the per-x constant vector (nc1+nc4)
// ---------------------------------------------------------------------------
__global__ void prep_kernel(const float* __restrict__ xm,
                            const float* __restrict__ xl) {
    int b = blockIdx.y;
    int x = blockIdx.x * 128 + threadIdx.x;
    const float* xmb = xm + b * Dn * TXn;
    const float* xlb = xl + b * Dn * TXn;
    float* bms = g_bms + b * Dn * TXn;
    float* bs  = g_bs  + b * Dn * TXn;
    float c = 0.0f;
    #pragma unroll 4
    for (int d = 0; d < Dn; d++) {
        float m = xmb[d * TXn + x];
        float l = xlb[d * TXn + x];
        float s = expf(-2.0f * l);
        bs [d * TXn + x] = s;
        bms[d * TXn + x] = m * s;
        c += (-l) + (-0.5f * m * m * s);
    }
    g_cvec[b * TXn + x] = c - (float)Dn * 0.91893853320467274f;
}

// ---------------------------------------------------------------------------
// Kernel 2: nc GEMM with packed f32x2 FMAs.
// nc[b,y,x] = sum_d z[d,y]*bms[d,x] + (-0.5 z^2)[d,y]*bs[d,x] + cvec[x]
// Tile 128(y) x 128(x), K-chunk 8, 256 threads, 8x8 microtile as 8x4 f32x2.
// A operands stored DUPLICATED in shared ((a,a) pairs) so no packing in the
// inner loop. Next chunk's global loads issue BEFORE compute (latency hidden).
// Band skip: bx>by tiles masked later; bx<=by-13 provably outside the DP
// dependency cone of the reachable band (deps never dip below x = y-1536).
// ---------------------------------------------------------------------------
__global__ __launch_bounds__(256) void nc_gemm_kernel(const float* __restrict__ z) {
    int bx = blockIdx.x;
    int by = blockIdx.y;
    int b  = blockIdx.z;
    if (bx > by) return;
    if (bx <= by - 13) return;

    __shared__ float2 s_zd[8][128];   // (z, z) duplicated
    __shared__ float2 s_z2[8][128];   // (-.5z^2, -.5z^2) duplicated
    __shared__ float  s_ms[8][128];
    __shared__ float  s_s [8][128];

    int tid = threadIdx.x;
    int lr = tid >> 5;            // 0..7  (k row for loads)
    int lc = (tid & 31) * 4;      // 0..124
    int ty = tid >> 4;            // 0..15
    int tx = tid & 15;            // 0..15

    const float* zb  = z     + b * Dn * TYn + by * 128;
    const float* msb = g_bms + b * Dn * TXn + bx * 128;
    const float* ssb = g_bs  + b * Dn * TXn + bx * 128;

    unsigned long long acc[8][4];
    #pragma unroll
    for (int i = 0; i < 8; i++)
        #pragma unroll
        for (int j = 0; j < 4; j++) acc[i][j] = 0ull;

    // prologue: load chunk 0
    float4 az  = *(const float4*)(zb  + lr * TYn + lc);
    float4 ams = *(const float4*)(msb + lr * TXn + lc);
    float4 ass = *(const float4*)(ssb + lr * TXn + lc);

    for (int c = 0; c < Dn / 8; c++) {
        __syncthreads();
        {
            float4* pz = (float4*)&s_zd[lr][lc];
            pz[0] = make_float4(az.x, az.x, az.y, az.y);
            pz[1] = make_float4(az.z, az.z, az.w, az.w);
            float zx = -0.5f * az.x * az.x, zy = -0.5f * az.y * az.y;
            float zz = -0.5f * az.z * az.z, zw = -0.5f * az.w * az.w;
            float4* p2 = (float4*)&s_z2[lr][lc];
            p2[0] = make_float4(zx, zx, zy, zy);
            p2[1] = make_float4(zz, zz, zw, zw);
            *(float4*)&s_ms[lr][lc] = ams;
            *(float4*)&s_s [lr][lc] = ass;
        }
        __syncthreads();

        if (c + 1 < Dn / 8) {       // issue next chunk's LDGs, hide under compute
            int d0 = (c + 1) * 8;
            az  = *(const float4*)(zb  + (d0 + lr) * TYn + lc);
            ams = *(const float4*)(msb + (d0 + lr) * TXn + lc);
            ass = *(const float4*)(ssb + (d0 + lr) * TXn + lc);
        }

        #pragma unroll
        for (int kk = 0; kk < 8; kk++) {
            unsigned long long a1[8], a2[8], b1[4], b2[4];
            {
                const ulonglong2* pa = (const ulonglong2*)&s_zd[kk][ty * 8];
                ulonglong2 t0 = pa[0], t1 = pa[1], t2 = pa[2], t3 = pa[3];
                a1[0]=t0.x; a1[1]=t0.y; a1[2]=t1.x; a1[3]=t1.y;
                a1[4]=t2.x; a1[5]=t2.y; a1[6]=t3.x; a1[7]=t3.y;
            }
            {
                const ulonglong2* pa = (const ulonglong2*)&s_z2[kk][ty * 8];
                ulonglong2 t0 = pa[0], t1 = pa[1], t2 = pa[2], t3 = pa[3];
                a2[0]=t0.x; a2[1]=t0.y; a2[2]=t1.x; a2[3]=t1.y;
                a2[4]=t2.x; a2[5]=t2.y; a2[6]=t3.x; a2[7]=t3.y;
            }
            {
                const ulonglong2* pb = (const ulonglong2*)&s_ms[kk][tx * 8];
                ulonglong2 t0 = pb[0], t1 = pb[1];
                b1[0]=t0.x; b1[1]=t0.y; b1[2]=t1.x; b1[3]=t1.y;
            }
            {
                const ulonglong2* pb = (const ulonglong2*)&s_s[kk][tx * 8];
                ulonglong2 t0 = pb[0], t1 = pb[1];
                b2[0]=t0.x; b2[1]=t0.y; b2[2]=t1.x; b2[3]=t1.y;
            }
            #pragma unroll
            for (int i = 0; i < 8; i++)
                #pragma unroll
                for (int j = 0; j < 4; j++) {
                    fma2(acc[i][j], a1[i], b1[j]);
                    fma2(acc[i][j], a2[i], b2[j]);
                }
        }
    }

    float cv[8];
    *(float4*)&cv[0] = *(const float4*)(g_cvec + b * TXn + bx * 128 + tx * 8);
    *(float4*)&cv[4] = *(const float4*)(g_cvec + b * TXn + bx * 128 + tx * 8 + 4);

    float* outp = g_nc + (size_t)b * TYn * TXn + (size_t)(by * 128 + ty * 8) * TXn
                + bx * 128 + tx * 8;
    #pragma unroll
    for (int i = 0; i < 8; i++) {
        float2 f0 = *(float2*)&acc[i][0];
        float2 f1 = *(float2*)&acc[i][1];
        float2 f2 = *(float2*)&acc[i][2];
        float2 f3 = *(float2*)&acc[i][3];
        float4 o0 = make_float4(f0.x + cv[0], f0.y + cv[1], f1.x + cv[2], f1.y + cv[3]);
        float4 o1 = make_float4(f2.x + cv[4], f2.y + cv[5], f3.x + cv[6], f3.y + cv[7]);
        *(float4*)(outp + (size_t)i * TXn)     = o0;
        *(float4*)(outp + (size_t)i * TXn + 4) = o1;
    }
}

// ---------------------------------------------------------------------------
// Kernel 3: MAS — one warp per batch, prefetch depth 3 (12 LDG.128 in flight).
// ---------------------------------------------------------------------------
#define MAS_STEP(Y, PF)                                                      \
  {                                                                          \
    float cur[16];                                                           \
    _Pragma("unroll") for (int i = 0; i < 16; i++) cur[i] = PF[i];           \
    int ldy = (Y) + 3; if (ldy > TYn - 1) ldy = TYn - 1;                     \
    const float4* r = (const float4*)(nc + (size_t)ldy * TXn + base);        \
    float4 t0 = r[0], t1 = r[1], t2 = r[2], t3 = r[3];                       \
    *(float4*)&PF[0] = t0;  *(float4*)&PF[4]  = t1;                          \
    *(float4*)&PF[8] = t2;  *(float4*)&PF[12] = t3;                          \
    float up  = __shfl_up_sync(0xffffffffu, v[15], 1);                       \
    float vd0 = (lane == 0) ? NEGV : up;                                     \
    unsigned int bits = (vd0 > v[0]) ? 1u : 0u;                              \
    float nv0 = cur[0] + fmaxf(v[0], vd0);                                   \
    _Pragma("unroll") for (int i = 15; i >= 1; i--) {                        \
      bits |= (v[i - 1] > v[i]) ? (1u << i) : 0u;                            \
      v[i] = cur[i] + fmaxf(v[i], v[i - 1]);                                 \
    }                                                                        \
    v[0] = nv0;                                                              \
    if ((Y) < TXn - 1) {                                                     \
      _Pragma("unroll") for (int i = 0; i < 16; i++)                         \
        if (base + i > (Y)) v[i] = NEGV;                                     \
    }                                                                        \
    s_dirs[(Y) * 32 + lane] = (unsigned short)bits;                          \
  }

__global__ void mas_kernel(const float* __restrict__ logw,
                           float* __restrict__ out_llen,
                           float* __restrict__ out_attn) {
    extern __shared__ unsigned short s_dirs[];   // [TYn][32] bit-packed, 128 KB
    __shared__ unsigned short path_sm[TYn];
    __shared__ int w_sm[TXn];

    int b = blockIdx.x;
    int lane = threadIdx.x;
    const float* nc = g_nc + (size_t)b * TYn * TXn;
    int base = lane * 16;

    float v[16];
    #pragma unroll
    for (int i = 0; i < 16; i++) v[i] = NEGV;
    if (lane == 0) v[0] = nc[0];

    float pfa[16], pfb[16], pfc[16];
    {
        const float4* r1 = (const float4*)(nc + (size_t)1 * TXn + base);
        const float4* r2 = (const float4*)(nc + (size_t)2 * TXn + base);
        const float4* r3 = (const float4*)(nc + (size_t)3 * TXn + base);
        *(float4*)&pfa[0] = r1[0]; *(float4*)&pfa[4] = r1[1];
        *(float4*)&pfa[8] = r1[2]; *(float4*)&pfa[12] = r1[3];
        *(float4*)&pfb[0] = r2[0]; *(float4*)&pfb[4] = r2[1];
        *(float4*)&pfb[8] = r2[2]; *(float4*)&pfb[12] = r2[3];
        *(float4*)&pfc[0] = r3[0]; *(float4*)&pfc[4] = r3[1];
        *(float4*)&pfc[8] = r3[2]; *(float4*)&pfc[12] = r3[3];
    }

    int y = 1;
    while (true) {
        MAS_STEP(y, pfa); if (++y >= TYn) break;
        MAS_STEP(y, pfb); if (++y >= TYn) break;
        MAS_STEP(y, pfc); if (++y >= TYn) break;
    }
    __syncwarp();

    // backtrack (lane 0)
    if (lane == 0) {
        int idx = TXn - 1;
        for (int yy = TYn - 1; yy >= 1; yy--) {
            path_sm[yy] = (unsigned short)idx;
            unsigned int wbits = s_dirs[yy * 32 + (idx >> 4)];
            idx -= (int)((wbits >> (idx & 15)) & 1u);
        }
        path_sm[0] = (unsigned short)idx;
    }
    __syncwarp();

    for (int x = lane; x < TXn; x += 32) w_sm[x] = 0;
    __syncwarp();

    for (int yy = lane; yy < TYn; yy += 32) {
        int px = path_sm[yy];
        g_path[b * TYn + yy] = px;
        atomicAdd(&w_sm[px], 1);
        out_attn[(size_t)b * TYn * TXn + (size_t)yy * TXn + px] = 1.0f;
    }
    __syncwarp();

    float part = 0.0f;
    for (int x = lane; x < TXn; x += 32) {
        float lw = logw[b * TXn + x];
        float d  = lw - logf((float)w_sm[x] + 1e-6f);
        part += d * d;
    }
    #pragma unroll
    for (int o = 16; o > 0; o >>= 1)
        part += __shfl_down_sync(0xffffffffu, part, o);
    if (lane == 0) out_llen[b] = part;
}

// ---------------------------------------------------------------------------
// Kernel 4: gather out_main[b,d,y] = x[b,d,path[b,y]], split over 8 D-chunks.
// ---------------------------------------------------------------------------
__global__ void gather_kernel(const float* __restrict__ xm,
                              const float* __restrict__ xl,
                              float* __restrict__ out_main) {
    int b  = blockIdx.y;
    int dc = blockIdx.z;              // 0..7, 24 d's each
    int y  = blockIdx.x * 256 + threadIdx.x;
    int px = g_path[b * TYn + y];
    const float* xmb = xm + b * Dn * TXn + px;
    const float* xlb = xl + b * Dn * TXn + px;
    float* o = out_main + (size_t)b * 2 * Dn * TYn + y;
    int d0 = dc * 24;
    #pragma unroll 4
    for (int d = d0; d < d0 + 24; d++)
        o[(size_t)d * TYn] = xmb[(size_t)d * TXn];
    #pragma unroll 4
    for (int d = d0; d < d0 + 24; d++)
        o[(size_t)(Dn + d) * TYn] = xlb[(size_t)d * TXn];
}

// ---------------------------------------------------------------------------
extern "C" void kernel_launch(void* const* d_in, const int* in_sizes, int n_in,
                              void* d_out, int out_size) {
    const float* xm   = (const float*)d_in[0];  // [B,D,TX]
    const float* xl   = (const float*)d_in[1];  // [B,D,TX]
    const float* z    = (const float*)d_in[2];  // [B,D,TY]
    const float* logw = (const float*)d_in[3];  // [B,1,TX]

    float* out       = (float*)d_out;
    const size_t OM  = (size_t)Bn * 2 * Dn * TYn;
    float* out_main  = out;
    float* out_llen  = out + OM;
    float* out_attn  = out + OM + Bn;

    cudaFuncSetAttribute(mas_kernel,
                         cudaFuncAttributeMaxDynamicSharedMemorySize,
                         TYn * 32 * (int)sizeof(unsigned short));

    prep_kernel<<<dim3(TXn / 128, Bn), 128>>>(xm, xl);
    nc_gemm_kernel<<<dim3(TXn / 128, TYn / 128, Bn), 256>>>(z);
    cudaMemsetAsync(out_attn, 0, (size_t)Bn * TYn * TXn * sizeof(float));
    mas_kernel<<<Bn, 32, TYn * 32 * (int)sizeof(unsigned short)>>>(logw, out_llen, out_attn);
    gather_kernel<<<dim3(TYn / 256, Bn, 8), 256>>>(xm, xl, out_main);
}

// round 3
// speedup vs baseline: 2.0146x; 1.2399x over previous
#include <cuda_runtime.h>
#include <math.h>

#define Bn  16
#define Dn  192
#define TXn 512
#define TYn 2048
#define NEGV (-1e9f)

// ---- scratch (device globals; no allocation allowed) ----
__device__ __align__(16) float g_nc  [Bn * TYn * TXn];  // 64 MB neg_cent
__device__ __align__(16) float g_bms [Bn * Dn * TXn];
__device__ __align__(16) float g_bs  [Bn * Dn * TXn];
__device__ __align__(16) float g_cvec[Bn * TXn];
__device__ int   g_path[Bn * TYn];
__device__ int   g_dummy_sink;

// packed fp32x2 FMA (Blackwell)
__device__ __forceinline__ void fma2(unsigned long long& d,
                                     unsigned long long a,
                                     unsigned long long b) {
    asm("fma.rn.f32x2 %0, %1, %2, %0;" : "+l"(d) : "l"(a), "l"(b));
}

// dummy launch: shifts the ncu capture slot onto mas_kernel
__global__ void dummy_kernel() { g_dummy_sink = 1; }

// ---------------------------------------------------------------------------
// Kernel 1: prep
// ---------------------------------------------------------------------------
__global__ void prep_kernel(const float* __restrict__ xm,
                            const float* __restrict__ xl) {
    int b = blockIdx.y;
    int x = blockIdx.x * 128 + threadIdx.x;
    const float* xmb = xm + b * Dn * TXn;
    const float* xlb = xl + b * Dn * TXn;
    float* bms = g_bms + b * Dn * TXn;
    float* bs  = g_bs  + b * Dn * TXn;
    float c = 0.0f;
    #pragma unroll 4
    for (int d = 0; d < Dn; d++) {
        float m = xmb[d * TXn + x];
        float l = xlb[d * TXn + x];
        float s = expf(-2.0f * l);
        bs [d * TXn + x] = s;
        bms[d * TXn + x] = m * s;
        c += (-l) + (-0.5f * m * m * s);
    }
    g_cvec[b * TXn + x] = c - (float)Dn * 0.91893853320467274f;
}

// ---------------------------------------------------------------------------
// Kernel 2: nc GEMM with packed f32x2 FMAs (unchanged from R2)
// ---------------------------------------------------------------------------
__global__ __launch_bounds__(256) void nc_gemm_kernel(const float* __restrict__ z) {
    int bx = blockIdx.x;
    int by = blockIdx.y;
    int b  = blockIdx.z;
    if (bx > by) return;
    if (bx <= by - 13) return;

    __shared__ float2 s_zd[8][128];
    __shared__ float2 s_z2[8][128];
    __shared__ float  s_ms[8][128];
    __shared__ float  s_s [8][128];

    int tid = threadIdx.x;
    int lr = tid >> 5;
    int lc = (tid & 31) * 4;
    int ty = tid >> 4;
    int tx = tid & 15;

    const float* zb  = z     + b * Dn * TYn + by * 128;
    const float* msb = g_bms + b * Dn * TXn + bx * 128;
    const float* ssb = g_bs  + b * Dn * TXn + bx * 128;

    unsigned long long acc[8][4];
    #pragma unroll
    for (int i = 0; i < 8; i++)
        #pragma unroll
        for (int j = 0; j < 4; j++) acc[i][j] = 0ull;

    float4 az  = *(const float4*)(zb  + lr * TYn + lc);
    float4 ams = *(const float4*)(msb + lr * TXn + lc);
    float4 ass = *(const float4*)(ssb + lr * TXn + lc);

    for (int c = 0; c < Dn / 8; c++) {
        __syncthreads();
        {
            float4* pz = (float4*)&s_zd[lr][lc];
            pz[0] = make_float4(az.x, az.x, az.y, az.y);
            pz[1] = make_float4(az.z, az.z, az.w, az.w);
            float zx = -0.5f * az.x * az.x, zy = -0.5f * az.y * az.y;
            float zz = -0.5f * az.z * az.z, zw = -0.5f * az.w * az.w;
            float4* p2 = (float4*)&s_z2[lr][lc];
            p2[0] = make_float4(zx, zx, zy, zy);
            p2[1] = make_float4(zz, zz, zw, zw);
            *(float4*)&s_ms[lr][lc] = ams;
            *(float4*)&s_s [lr][lc] = ass;
        }
        __syncthreads();

        if (c + 1 < Dn / 8) {
            int d0 = (c + 1) * 8;
            az  = *(const float4*)(zb  + (d0 + lr) * TYn + lc);
            ams = *(const float4*)(msb + (d0 + lr) * TXn + lc);
            ass = *(const float4*)(ssb + (d0 + lr) * TXn + lc);
        }

        #pragma unroll
        for (int kk = 0; kk < 8; kk++) {
            unsigned long long a1[8], a2[8], b1[4], b2[4];
            {
                const ulonglong2* pa = (const ulonglong2*)&s_zd[kk][ty * 8];
                ulonglong2 t0 = pa[0], t1 = pa[1], t2 = pa[2], t3 = pa[3];
                a1[0]=t0.x; a1[1]=t0.y; a1[2]=t1.x; a1[3]=t1.y;
                a1[4]=t2.x; a1[5]=t2.y; a1[6]=t3.x; a1[7]=t3.y;
            }
            {
                const ulonglong2* pa = (const ulonglong2*)&s_z2[kk][ty * 8];
                ulonglong2 t0 = pa[0], t1 = pa[1], t2 = pa[2], t3 = pa[3];
                a2[0]=t0.x; a2[1]=t0.y; a2[2]=t1.x; a2[3]=t1.y;
                a2[4]=t2.x; a2[5]=t2.y; a2[6]=t3.x; a2[7]=t3.y;
            }
            {
                const ulonglong2* pb = (const ulonglong2*)&s_ms[kk][tx * 8];
                ulonglong2 t0 = pb[0], t1 = pb[1];
                b1[0]=t0.x; b1[1]=t0.y; b1[2]=t1.x; b1[3]=t1.y;
            }
            {
                const ulonglong2* pb = (const ulonglong2*)&s_s[kk][tx * 8];
                ulonglong2 t0 = pb[0], t1 = pb[1];
                b2[0]=t0.x; b2[1]=t0.y; b2[2]=t1.x; b2[3]=t1.y;
            }
            #pragma unroll
            for (int i = 0; i < 8; i++)
                #pragma unroll
                for (int j = 0; j < 4; j++) {
                    fma2(acc[i][j], a1[i], b1[j]);
                    fma2(acc[i][j], a2[i], b2[j]);
                }
        }
    }

    float cv[8];
    *(float4*)&cv[0] = *(const float4*)(g_cvec + b * TXn + bx * 128 + tx * 8);
    *(float4*)&cv[4] = *(const float4*)(g_cvec + b * TXn + bx * 128 + tx * 8 + 4);

    float* outp = g_nc + (size_t)b * TYn * TXn + (size_t)(by * 128 + ty * 8) * TXn
                + bx * 128 + tx * 8;
    #pragma unroll
    for (int i = 0; i < 8; i++) {
        float2 f0 = *(float2*)&acc[i][0];
        float2 f1 = *(float2*)&acc[i][1];
        float2 f2 = *(float2*)&acc[i][2];
        float2 f3 = *(float2*)&acc[i][3];
        float4 o0 = make_float4(f0.x + cv[0], f0.y + cv[1], f1.x + cv[2], f1.y + cv[3]);
        float4 o1 = make_float4(f2.x + cv[4], f2.y + cv[5], f3.x + cv[6], f3.y + cv[7]);
        *(float4*)(outp + (size_t)i * TXn)     = o0;
        *(float4*)(outp + (size_t)i * TXn + 4) = o1;
    }
}

// ---------------------------------------------------------------------------
// Kernel 3: MAS — halo-parallel. 4 warps/batch, each warp owns 128 cols and
// redundantly computes a 128-col left halo (8 cols/lane). Left-edge NEG
// poison propagates 1 col/row, so an exact boundary exchange every 64 rows
// keeps all OWNED columns bit-exact. No per-row sync.
// ---------------------------------------------------------------------------
#define MAS_ROW(Y, B0, B1)                                                   \
  {                                                                          \
    float cur[8];                                                            \
    cur[0]=B0.x; cur[1]=B0.y; cur[2]=B0.z; cur[3]=B0.w;                      \
    cur[4]=B1.x; cur[5]=B1.y; cur[6]=B1.z; cur[7]=B1.w;                      \
    int ldy = (Y) + 4; if (ldy > TYn - 1) ldy = TYn - 1;                     \
    B0 = *(const float4*)(lp + (size_t)ldy * TXn);                           \
    B1 = *(const float4*)(lp + (size_t)ldy * TXn + 4);                       \
    float lv = __shfl_up_sync(0xffffffffu, v[7], 1);                         \
    if (lane == 0) lv = NEGV;                                                \
    unsigned int bits = (lv > v[0]) ? 1u : 0u;                               \
    float nv0 = cur[0] + fmaxf(v[0], lv);                                    \
    _Pragma("unroll") for (int i = 7; i >= 1; i--) {                         \
      bits |= (v[i - 1] > v[i]) ? (1u << i) : 0u;                            \
      v[i] = cur[i] + fmaxf(v[i], v[i - 1]);                                 \
    }                                                                        \
    v[0] = nv0;                                                              \
    if ((Y) < TXn - 1) {                                                     \
      int ylim = (Y) - c0;                                                   \
      _Pragma("unroll") for (int i = 0; i < 8; i++)                          \
        if (i > ylim) v[i] = NEGV;                                           \
    }                                                                        \
    if (lane >= 16)                                                          \
      s_dirs[(Y) * 64 + w * 16 + (lane - 16)] = (unsigned char)bits;         \
  }

#define MAS_EXCH()                                                           \
  {                                                                          \
    if (lane >= 16) {                                                        \
      *(float4*)&s_exch[w * 128 + (lane - 16) * 8]                           \
          = make_float4(v[0], v[1], v[2], v[3]);                             \
      *(float4*)&s_exch[w * 128 + (lane - 16) * 8 + 4]                       \
          = make_float4(v[4], v[5], v[6], v[7]);                             \
    }                                                                        \
    __syncthreads();                                                         \
    if (w > 0 && lane < 16) {                                                \
      float4 e0 = *(const float4*)&s_exch[(w - 1) * 128 + lane * 8];         \
      float4 e1 = *(const float4*)&s_exch[(w - 1) * 128 + lane * 8 + 4];     \
      v[0]=e0.x; v[1]=e0.y; v[2]=e0.z; v[3]=e0.w;                            \
      v[4]=e1.x; v[5]=e1.y; v[6]=e1.z; v[7]=e1.w;                            \
    }                                                                        \
    __syncthreads();                                                         \
  }

__global__ __launch_bounds__(128) void mas_kernel(const float* __restrict__ logw,
                                                  float* __restrict__ out_llen,
                                                  float* __restrict__ out_attn) {
    extern __shared__ unsigned char s_dirs[];   // [TYn][64] = 128 KB
    __shared__ float s_exch[4 * 128];
    __shared__ unsigned short path_sm[TYn];
    __shared__ int w_sm[TXn];
    __shared__ float s_red[4];

    int b = blockIdx.x;
    int tid = threadIdx.x;
    int w = tid >> 5, lane = tid & 31;
    const float* nc = g_nc + (size_t)b * TYn * TXn;
    int cbase = (w - 1) * 128;
    int c0 = cbase + lane * 8;                  // may be negative (warp0 halo)
    int ldoff = c0 < 0 ? 0 : c0;
    const float* lp = nc + ldoff;

    float v[8];
    #pragma unroll
    for (int i = 0; i < 8; i++) v[i] = NEGV;
    if (c0 == 0) v[0] = nc[0];                  // row-0 init: only x==0 live

    // preload rows 1..4
    float4 bA0 = *(const float4*)(lp + 1 * TXn), bA1 = *(const float4*)(lp + 1 * TXn + 4);
    float4 bB0 = *(const float4*)(lp + 2 * TXn), bB1 = *(const float4*)(lp + 2 * TXn + 4);
    float4 bC0 = *(const float4*)(lp + 3 * TXn), bC1 = *(const float4*)(lp + 3 * TXn + 4);
    float4 bD0 = *(const float4*)(lp + 4 * TXn), bD1 = *(const float4*)(lp + 4 * TXn + 4);

    int y = 1;
    for (;;) {
        MAS_ROW(y, bA0, bA1); if ((y & 63) == 0) MAS_EXCH(); if (++y >= TYn) break;
        MAS_ROW(y, bB0, bB1); if ((y & 63) == 0) MAS_EXCH(); if (++y >= TYn) break;
        MAS_ROW(y, bC0, bC1); if ((y & 63) == 0) MAS_EXCH(); if (++y >= TYn) break;
        MAS_ROW(y, bD0, bD1); if ((y & 63) == 0) MAS_EXCH(); if (++y >= TYn) break;
    }
    __syncthreads();

    // serial backtrack (bit for col x at byte x>>3, bit x&7)
    if (tid == 0) {
        int idx = TXn - 1;
        for (int yy = TYn - 1; yy >= 1; yy--) {
            path_sm[yy] = (unsigned short)idx;
            idx -= (int)((s_dirs[yy * 64 + (idx >> 3)] >> (idx & 7)) & 1u);
        }
        path_sm[0] = (unsigned short)idx;
    }
    __syncthreads();

    for (int x = tid; x < TXn; x += 128) w_sm[x] = 0;
    __syncthreads();

    for (int yy = tid; yy < TYn; yy += 128) {
        int px = path_sm[yy];
        g_path[b * TYn + yy] = px;
        atomicAdd(&w_sm[px], 1);
        out_attn[(size_t)b * TYn * TXn + (size_t)yy * TXn + px] = 1.0f;
    }
    __syncthreads();

    float part = 0.0f;
    for (int x = tid; x < TXn; x += 128) {
        float lw = logw[b * TXn + x];
        float d  = lw - logf((float)w_sm[x] + 1e-6f);
        part += d * d;
    }
    #pragma unroll
    for (int o = 16; o > 0; o >>= 1)
        part += __shfl_down_sync(0xffffffffu, part, o);
    if (lane == 0) s_red[w] = part;
    __syncthreads();
    if (tid == 0) out_llen[b] = s_red[0] + s_red[1] + s_red[2] + s_red[3];
}

// ---------------------------------------------------------------------------
// Kernel 4: gather
// ---------------------------------------------------------------------------
__global__ void gather_kernel(const float* __restrict__ xm,
                              const float* __restrict__ xl,
                              float* __restrict__ out_main) {
    int b  = blockIdx.y;
    int dc = blockIdx.z;
    int y  = blockIdx.x * 256 + threadIdx.x;
    int px = g_path[b * TYn + y];
    const float* xmb = xm + b * Dn * TXn + px;
    const float* xlb = xl + b * Dn * TXn + px;
    float* o = out_main + (size_t)b * 2 * Dn * TYn + y;
    int d0 = dc * 24;
    #pragma unroll 4
    for (int d = d0; d < d0 + 24; d++)
        o[(size_t)d * TYn] = xmb[(size_t)d * TXn];
    #pragma unroll 4
    for (int d = d0; d < d0 + 24; d++)
        o[(size_t)(Dn + d) * TYn] = xlb[(size_t)d * TXn];
}

// ---------------------------------------------------------------------------
extern "C" void kernel_launch(void* const* d_in, const int* in_sizes, int n_in,
                              void* d_out, int out_size) {
    const float* xm   = (const float*)d_in[0];
    const float* xl   = (const float*)d_in[1];
    const float* z    = (const float*)d_in[2];
    const float* logw = (const float*)d_in[3];

    float* out       = (float*)d_out;
    const size_t OM  = (size_t)Bn * 2 * Dn * TYn;
    float* out_main  = out;
    float* out_llen  = out + OM;
    float* out_attn  = out + OM + Bn;

    cudaFuncSetAttribute(mas_kernel,
                         cudaFuncAttributeMaxDynamicSharedMemorySize,
                         TYn * 64);

    dummy_kernel<<<1, 1>>>();
    prep_kernel<<<dim3(TXn / 128, Bn), 128>>>(xm, xl);
    nc_gemm_kernel<<<dim3(TXn / 128, TYn / 128, Bn), 256>>>(z);
    cudaMemsetAsync(out_attn, 0, (size_t)Bn * TYn * TXn * sizeof(float));
    mas_kernel<<<Bn, 128, TYn * 64>>>(logw, out_llen, out_attn);
    gather_kernel<<<dim3(TYn / 256, Bn, 8), 256>>>(xm, xl, out_main);
}

// round 4
// speedup vs baseline: 2.7389x; 1.3595x over previous
#include <cuda_runtime.h>
#include <math.h>

#define Bn  16
#define Dn  192
#define TXn 512
#define TYn 2048
#define NEGV (-1e9f)

// ---- scratch (device globals; no allocation allowed) ----
__device__ __align__(16) float g_nc  [Bn * TYn * TXn];  // 64 MB neg_cent
__device__ __align__(16) float g_bms [Bn * Dn * TXn];
__device__ __align__(16) float g_bs  [Bn * Dn * TXn];
__device__ __align__(16) float g_cvec[Bn * TXn];
__device__ int   g_path[Bn * TYn];
__device__ int   g_dummy_sink;

// packed fp32x2 FMA (Blackwell)
__device__ __forceinline__ void fma2(unsigned long long& d,
                                     unsigned long long a,
                                     unsigned long long b) {
    asm("fma.rn.f32x2 %0, %1, %2, %0;" : "+l"(d) : "l"(a), "l"(b));
}

__device__ __forceinline__ void cp16(float* dst_smem, const float* src) {
    unsigned int d = (unsigned int)__cvta_generic_to_shared(dst_smem);
    asm volatile("cp.async.cg.shared.global [%0], [%1], 16;" :: "r"(d), "l"(src));
}
#define CP_COMMIT() asm volatile("cp.async.commit_group;")
#define CP_WAIT1()  asm volatile("cp.async.wait_group 1;" ::: "memory")

// dummy launches: shift the ncu capture slot (4th kernel) onto nc_gemm_kernel
__global__ void dummy_kernel() { g_dummy_sink = 1; }

// ---------------------------------------------------------------------------
// Kernel 1: prep
// ---------------------------------------------------------------------------
__global__ void prep_kernel(const float* __restrict__ xm,
                            const float* __restrict__ xl) {
    int b = blockIdx.y;
    int x = blockIdx.x * 128 + threadIdx.x;
    const float* xmb = xm + b * Dn * TXn;
    const float* xlb = xl + b * Dn * TXn;
    float* bms = g_bms + b * Dn * TXn;
    float* bs  = g_bs  + b * Dn * TXn;
    float c = 0.0f;
    #pragma unroll 4
    for (int d = 0; d < Dn; d++) {
        float m = xmb[d * TXn + x];
        float l = xlb[d * TXn + x];
        float s = expf(-2.0f * l);
        bs [d * TXn + x] = s;
        bms[d * TXn + x] = m * s;
        c += (-l) + (-0.5f * m * m * s);
    }
    g_cvec[b * TXn + x] = c - (float)Dn * 0.91893853320467274f;
}

// ---------------------------------------------------------------------------
// Kernel 2: nc GEMM with packed f32x2 FMAs (unchanged)
// ---------------------------------------------------------------------------
__global__ __launch_bounds__(256) void nc_gemm_kernel(const float* __restrict__ z) {
    int bx = blockIdx.x;
    int by = blockIdx.y;
    int b  = blockIdx.z;
    if (bx > by) return;
    if (bx <= by - 13) return;

    __shared__ float2 s_zd[8][128];
    __shared__ float2 s_z2[8][128];
    __shared__ float  s_ms[8][128];
    __shared__ float  s_s [8][128];

    int tid = threadIdx.x;
    int lr = tid >> 5;
    int lc = (tid & 31) * 4;
    int ty = tid >> 4;
    int tx = tid & 15;

    const float* zb  = z     + b * Dn * TYn + by * 128;
    const float* msb = g_bms + b * Dn * TXn + bx * 128;
    const float* ssb = g_bs  + b * Dn * TXn + bx * 128;

    unsigned long long acc[8][4];
    #pragma unroll
    for (int i = 0; i < 8; i++)
        #pragma unroll
        for (int j = 0; j < 4; j++) acc[i][j] = 0ull;

    float4 az  = *(const float4*)(zb  + lr * TYn + lc);
    float4 ams = *(const float4*)(msb + lr * TXn + lc);
    float4 ass = *(const float4*)(ssb + lr * TXn + lc);

    for (int c = 0; c < Dn / 8; c++) {
        __syncthreads();
        {
            float4* pz = (float4*)&s_zd[lr][lc];
            pz[0] = make_float4(az.x, az.x, az.y, az.y);
            pz[1] = make_float4(az.z, az.z, az.w, az.w);
            float zx = -0.5f * az.x * az.x, zy = -0.5f * az.y * az.y;
            float zz = -0.5f * az.z * az.z, zw = -0.5f * az.w * az.w;
            float4* p2 = (float4*)&s_z2[lr][lc];
            p2[0] = make_float4(zx, zx, zy, zy);
            p2[1] = make_float4(zz, zz, zw, zw);
            *(float4*)&s_ms[lr][lc] = ams;
            *(float4*)&s_s [lr][lc] = ass;
        }
        __syncthreads();

        if (c + 1 < Dn / 8) {
            int d0 = (c + 1) * 8;
            az  = *(const float4*)(zb  + (d0 + lr) * TYn + lc);
            ams = *(const float4*)(msb + (d0 + lr) * TXn + lc);
            ass = *(const float4*)(ssb + (d0 + lr) * TXn + lc);
        }

        #pragma unroll
        for (int kk = 0; kk < 8; kk++) {
            unsigned long long a1[8], a2[8], b1[4], b2[4];
            {
                const ulonglong2* pa = (const ulonglong2*)&s_zd[kk][ty * 8];
                ulonglong2 t0 = pa[0], t1 = pa[1], t2 = pa[2], t3 = pa[3];
                a1[0]=t0.x; a1[1]=t0.y; a1[2]=t1.x; a1[3]=t1.y;
                a1[4]=t2.x; a1[5]=t2.y; a1[6]=t3.x; a1[7]=t3.y;
            }
            {
                const ulonglong2* pa = (const ulonglong2*)&s_z2[kk][ty * 8];
                ulonglong2 t0 = pa[0], t1 = pa[1], t2 = pa[2], t3 = pa[3];
                a2[0]=t0.x; a2[1]=t0.y; a2[2]=t1.x; a2[3]=t1.y;
                a2[4]=t2.x; a2[5]=t2.y; a2[6]=t3.x; a2[7]=t3.y;
            }
            {
                const ulonglong2* pb = (const ulonglong2*)&s_ms[kk][tx * 8];
                ulonglong2 t0 = pb[0], t1 = pb[1];
                b1[0]=t0.x; b1[1]=t0.y; b1[2]=t1.x; b1[3]=t1.y;
            }
            {
                const ulonglong2* pb = (const ulonglong2*)&s_s[kk][tx * 8];
                ulonglong2 t0 = pb[0], t1 = pb[1];
                b2[0]=t0.x; b2[1]=t0.y; b2[2]=t1.x; b2[3]=t1.y;
            }
            #pragma unroll
            for (int i = 0; i < 8; i++)
                #pragma unroll
                for (int j = 0; j < 4; j++) {
                    fma2(acc[i][j], a1[i], b1[j]);
                    fma2(acc[i][j], a2[i], b2[j]);
                }
        }
    }

    float cv[8];
    *(float4*)&cv[0] = *(const float4*)(g_cvec + b * TXn + bx * 128 + tx * 8);
    *(float4*)&cv[4] = *(const float4*)(g_cvec + b * TXn + bx * 128 + tx * 8 + 4);

    float* outp = g_nc + (size_t)b * TYn * TXn + (size_t)(by * 128 + ty * 8) * TXn
                + bx * 128 + tx * 8;
    #pragma unroll
    for (int i = 0; i < 8; i++) {
        float2 f0 = *(float2*)&acc[i][0];
        float2 f1 = *(float2*)&acc[i][1];
        float2 f2 = *(float2*)&acc[i][2];
        float2 f3 = *(float2*)&acc[i][3];
        float4 o0 = make_float4(f0.x + cv[0], f0.y + cv[1], f1.x + cv[2], f1.y + cv[3]);
        float4 o1 = make_float4(f2.x + cv[4], f2.y + cv[5], f3.x + cv[6], f3.y + cv[7]);
        *(float4*)(outp + (size_t)i * TXn)     = o0;
        *(float4*)(outp + (size_t)i * TXn + 4) = o1;
    }
}

// ---------------------------------------------------------------------------
// Kernel 3: MAS — halo-parallel DP fed by a cp.async double-buffered smem
// pipeline (16-row chunks). Per-chunk __syncthreads subsumes halo exchanges.
// ---------------------------------------------------------------------------
#define MAS_ROW_S(Y, TB)                                                     \
  {                                                                          \
    const float* rp = (TB) + ((Y) & 15) * TXn + ldoff;                       \
    float4 B0 = *(const float4*)rp;                                          \
    float4 B1 = *(const float4*)(rp + 4);                                    \
    float cur[8];                                                            \
    cur[0]=B0.x; cur[1]=B0.y; cur[2]=B0.z; cur[3]=B0.w;                      \
    cur[4]=B1.x; cur[5]=B1.y; cur[6]=B1.z; cur[7]=B1.w;                      \
    float lv = __shfl_up_sync(0xffffffffu, v[7], 1);                         \
    if (lane == 0) lv = NEGV;                                                \
    unsigned int bits = (lv > v[0]) ? 1u : 0u;                               \
    float nv0 = cur[0] + fmaxf(v[0], lv);                                    \
    _Pragma("unroll") for (int i = 7; i >= 1; i--) {                         \
      bits |= (v[i - 1] > v[i]) ? (1u << i) : 0u;                            \
      v[i] = cur[i] + fmaxf(v[i], v[i - 1]);                                 \
    }                                                                        \
    v[0] = nv0;                                                              \
    if ((Y) < TXn - 1) {                                                     \
      int ylim = (Y) - c0;                                                   \
      _Pragma("unroll") for (int i = 0; i < 8; i++)                          \
        if (i > ylim) v[i] = NEGV;                                           \
    }                                                                        \
    if (lane >= 16)                                                          \
      s_dirs[(Y) * 64 + w * 16 + (lane - 16)] = (unsigned char)bits;         \
  }

#define MAS_EXCH()                                                           \
  {                                                                          \
    if (lane >= 16) {                                                        \
      *(float4*)&s_exch[w * 128 + (lane - 16) * 8]                           \
          = make_float4(v[0], v[1], v[2], v[3]);                             \
      *(float4*)&s_exch[w * 128 + (lane - 16) * 8 + 4]                       \
          = make_float4(v[4], v[5], v[6], v[7]);                             \
    }                                                                        \
    __syncthreads();                                                         \
    if (w > 0 && lane < 16) {                                                \
      float4 e0 = *(const float4*)&s_exch[(w - 1) * 128 + lane * 8];         \
      float4 e1 = *(const float4*)&s_exch[(w - 1) * 128 + lane * 8 + 4];     \
      v[0]=e0.x; v[1]=e0.y; v[2]=e0.z; v[3]=e0.w;                            \
      v[4]=e1.x; v[5]=e1.y; v[6]=e1.z; v[7]=e1.w;                            \
    }                                                                        \
    __syncthreads();                                                         \
  }

#define LOAD_CHUNK(C, BUF)                                                   \
  {                                                                          \
    const float* src = nc + (size_t)(C) * 16 * TXn;                          \
    float* dstb = (BUF);                                                     \
    _Pragma("unroll") for (int i = 0; i < 16; i++)                           \
      cp16(dstb + (tid + i * 128) * 4, src + (tid + i * 128) * 4);           \
    CP_COMMIT();                                                             \
  }

__global__ __launch_bounds__(128) void mas_kernel(const float* __restrict__ logw,
                                                  float* __restrict__ out_llen,
                                                  float* __restrict__ out_attn) {
    extern __shared__ unsigned char s_dyn[];
    unsigned char* s_dirs = s_dyn;                       // 2048*64 = 128 KB
    float* tileA = (float*)(s_dyn + TYn * 64);           // 16*512*4 = 32 KB
    float* tileB = tileA + 16 * TXn;                     // 32 KB
    __shared__ float s_exch[4 * 128];
    __shared__ unsigned short path_sm[TYn];
    __shared__ int w_sm[TXn];
    __shared__ float s_red[4];

    int b = blockIdx.x;
    int tid = threadIdx.x;
    int w = tid >> 5, lane = tid & 31;
    const float* nc = g_nc + (size_t)b * TYn * TXn;
    int cbase = (w - 1) * 128;
    int c0 = cbase + lane * 8;                  // may be negative (warp0 halo)
    int ldoff = c0 < 0 ? 0 : c0;

    float v[8];
    #pragma unroll
    for (int i = 0; i < 8; i++) v[i] = NEGV;
    if (c0 == 0) v[0] = nc[0];

    LOAD_CHUNK(0, tileA);
    LOAD_CHUNK(1, tileB);

    int y = 1;
    for (int c = 0; c < TYn / 16; c++) {
        CP_WAIT1();
        __syncthreads();
        float* tb = (c & 1) ? tileB : tileA;
        int yend = c * 16 + 16;
        #pragma unroll 4
        for (; y < yend; y++) MAS_ROW_S(y, tb);
        __syncthreads();
        if (c + 2 < TYn / 16) LOAD_CHUNK(c + 2, tb);
        if ((c & 3) == 3 && c + 1 < TYn / 16) MAS_EXCH();
    }
    __syncthreads();

    // serial backtrack (bit for col x at byte x>>3, bit x&7)
    if (tid == 0) {
        int idx = TXn - 1;
        for (int yy = TYn - 1; yy >= 1; yy--) {
            path_sm[yy] = (unsigned short)idx;
            idx -= (int)((s_dirs[yy * 64 + (idx >> 3)] >> (idx & 7)) & 1u);
        }
        path_sm[0] = (unsigned short)idx;
    }
    __syncthreads();

    for (int x = tid; x < TXn; x += 128) w_sm[x] = 0;
    __syncthreads();

    for (int yy = tid; yy < TYn; yy += 128) {
        int px = path_sm[yy];
        g_path[b * TYn + yy] = px;
        atomicAdd(&w_sm[px], 1);
        out_attn[(size_t)b * TYn * TXn + (size_t)yy * TXn + px] = 1.0f;
    }
    __syncthreads();

    float part = 0.0f;
    for (int x = tid; x < TXn; x += 128) {
        float lw = logw[b * TXn + x];
        float d  = lw - logf((float)w_sm[x] + 1e-6f);
        part += d * d;
    }
    #pragma unroll
    for (int o = 16; o > 0; o >>= 1)
        part += __shfl_down_sync(0xffffffffu, part, o);
    if (lane == 0) s_red[w] = part;
    __syncthreads();
    if (tid == 0) out_llen[b] = s_red[0] + s_red[1] + s_red[2] + s_red[3];
}

// ---------------------------------------------------------------------------
// Kernel 4: gather
// ---------------------------------------------------------------------------
__global__ void gather_kernel(const float* __restrict__ xm,
                              const float* __restrict__ xl,
                              float* __restrict__ out_main) {
    int b  = blockIdx.y;
    int dc = blockIdx.z;
    int y  = blockIdx.x * 256 + threadIdx.x;
    int px = g_path[b * TYn + y];
    const float* xmb = xm + b * Dn * TXn + px;
    const float* xlb = xl + b * Dn * TXn + px;
    float* o = out_main + (size_t)b * 2 * Dn * TYn + y;
    int d0 = dc * 24;
    #pragma unroll 4
    for (int d = d0; d < d0 + 24; d++)
        o[(size_t)d * TYn] = xmb[(size_t)d * TXn];
    #pragma unroll 4
    for (int d = d0; d < d0 + 24; d++)
        o[(size_t)(Dn + d) * TYn] = xlb[(size_t)d * TXn];
}

// ---------------------------------------------------------------------------
extern "C" void kernel_launch(void* const* d_in, const int* in_sizes, int n_in,
                              void* d_out, int out_size) {
    const float* xm   = (const float*)d_in[0];
    const float* xl   = (const float*)d_in[1];
    const float* z    = (const float*)d_in[2];
    const float* logw = (const float*)d_in[3];

    float* out       = (float*)d_out;
    const size_t OM  = (size_t)Bn * 2 * Dn * TYn;
    float* out_main  = out;
    float* out_llen  = out + OM;
    float* out_attn  = out + OM + Bn;

    cudaFuncSetAttribute(mas_kernel,
                         cudaFuncAttributeMaxDynamicSharedMemorySize,
                         TYn * 64 + 2 * 16 * TXn * (int)sizeof(float));

    dummy_kernel<<<1, 1>>>();
    dummy_kernel<<<1, 1>>>();
    prep_kernel<<<dim3(TXn / 128, Bn), 128>>>(xm, xl);
    nc_gemm_kernel<<<dim3(TXn / 128, TYn / 128, Bn), 256>>>(z);
    cudaMemsetAsync(out_attn, 0, (size_t)Bn * TYn * TXn * sizeof(float));
    mas_kernel<<<Bn, 128, TYn * 64 + 2 * 16 * TXn * (int)sizeof(float)>>>(logw, out_llen, out_attn);
    gather_kernel<<<dim3(TYn / 256, Bn, 8), 256>>>(xm, xl, out_main);
}

// round 5
// speedup vs baseline: 3.0049x; 1.0971x over previous
#include <cuda_runtime.h>
#include <math.h>

#define Bn  16
#define Dn  192
#define TXn 512
#define TYn 2048
#define NEGV (-1e9f)

// ---- scratch (device globals; no allocation allowed) ----
__device__ __align__(16) float g_nc  [Bn * TYn * TXn];  // 64 MB neg_cent
__device__ __align__(16) float g_bms [Bn * Dn * TXn];
__device__ __align__(16) float g_bs  [Bn * Dn * TXn];
__device__ __align__(16) float g_cvec[Bn * TXn];
__device__ __align__(16) float g_cpart[8 * Bn * TXn];
__device__ int   g_path[Bn * TYn];

// packed fp32x2 FMA (Blackwell)
__device__ __forceinline__ void fma2(unsigned long long& d,
                                     unsigned long long a,
                                     unsigned long long b) {
    asm("fma.rn.f32x2 %0, %1, %2, %0;" : "+l"(d) : "l"(a), "l"(b));
}

__device__ __forceinline__ void cp16(float* dst_smem, const float* src) {
    unsigned int d = (unsigned int)__cvta_generic_to_shared(dst_smem);
    asm volatile("cp.async.cg.shared.global [%0], [%1], 16;" :: "r"(d), "l"(src));
}
#define CP_COMMIT() asm volatile("cp.async.commit_group;")
#define CP_WAIT1()  asm volatile("cp.async.wait_group 1;" ::: "memory")

// ---------------------------------------------------------------------------
// Kernel 1: prep — 8 D-chunks in parallel, deterministic partials
// ---------------------------------------------------------------------------
__global__ void prep_kernel(const float* __restrict__ xm,
                            const float* __restrict__ xl) {
    int b  = blockIdx.y;
    int dc = blockIdx.z;                    // 0..7
    int x  = blockIdx.x * 128 + threadIdx.x;
    const float* xmb = xm + b * Dn * TXn;
    const float* xlb = xl + b * Dn * TXn;
    float* bms = g_bms + b * Dn * TXn;
    float* bs  = g_bs  + b * Dn * TXn;
    float c = 0.0f;
    int d0 = dc * 24;
    #pragma unroll 4
    for (int d = d0; d < d0 + 24; d++) {
        float m = xmb[d * TXn + x];
        float l = xlb[d * TXn + x];
        float s = expf(-2.0f * l);
        bs [d * TXn + x] = s;
        bms[d * TXn + x] = m * s;
        c += (-l) + (-0.5f * m * m * s);
    }
    g_cpart[dc * (Bn * TXn) + b * TXn + x] = c;
}

// Kernel 1b: deterministic combine of the 8 partials + nc1 constant
__global__ void combine_kernel() {
    int i = blockIdx.x * 256 + threadIdx.x;     // 0..Bn*TXn-1
    float c = -(float)Dn * 0.91893853320467274f;
    #pragma unroll
    for (int p = 0; p < 8; p++) c += g_cpart[p * (Bn * TXn) + i];
    g_cvec[i] = c;
}

// ---------------------------------------------------------------------------
// Kernel 2: nc GEMM, packed f32x2 FMAs.
// A (z side) pre-duplicated in smem (reads are 2-ty broadcast -> ~free).
// B (x side) stored lo/hi SPLIT per k-row so a warp's LDS.128 covers a
// contiguous 256B -> 2 phases (was 4-way conflicted).
// ---------------------------------------------------------------------------
__global__ __launch_bounds__(256) void nc_gemm_kernel(const float* __restrict__ z) {
    int bx = blockIdx.x;
    int by = blockIdx.y;
    int b  = blockIdx.z;
    if (bx > by) return;
    if (bx <= by - 13) return;

    __shared__ float2 s_zd[8][128];   // (z,z) duplicated
    __shared__ float2 s_z2[8][128];   // (-.5z^2, -.5z^2) duplicated
    __shared__ float  s_ms[8][128];   // split layout: [lo 64 | hi 64]
    __shared__ float  s_s [8][128];   // split layout

    int tid = threadIdx.x;
    int lr = tid >> 5;
    int lc = (tid & 31) * 4;
    int ty = tid >> 4;
    int tx = tid & 15;
    int bsplit = ((lc >> 2) & 1) * 64 + (lc >> 3) * 4;   // split-layout dst

    const float* zb  = z     + b * Dn * TYn + by * 128;
    const float* msb = g_bms + b * Dn * TXn + bx * 128;
    const float* ssb = g_bs  + b * Dn * TXn + bx * 128;

    unsigned long long acc[8][4];
    #pragma unroll
    for (int i = 0; i < 8; i++)
        #pragma unroll
        for (int j = 0; j < 4; j++) acc[i][j] = 0ull;

    float4 az  = *(const float4*)(zb  + lr * TYn + lc);
    float4 ams = *(const float4*)(msb + lr * TXn + lc);
    float4 ass = *(const float4*)(ssb + lr * TXn + lc);

    for (int c = 0; c < Dn / 8; c++) {
        __syncthreads();
        {
            float4* pz = (float4*)&s_zd[lr][lc];
            pz[0] = make_float4(az.x, az.x, az.y, az.y);
            pz[1] = make_float4(az.z, az.z, az.w, az.w);
            float zx = -0.5f * az.x * az.x, zy = -0.5f * az.y * az.y;
            float zz = -0.5f * az.z * az.z, zw = -0.5f * az.w * az.w;
            float4* p2 = (float4*)&s_z2[lr][lc];
            p2[0] = make_float4(zx, zx, zy, zy);
            p2[1] = make_float4(zz, zz, zw, zw);
            *(float4*)&s_ms[lr][bsplit] = ams;
            *(float4*)&s_s [lr][bsplit] = ass;
        }
        __syncthreads();

        if (c + 1 < Dn / 8) {
            int d0 = (c + 1) * 8;
            az  = *(const float4*)(zb  + (d0 + lr) * TYn + lc);
            ams = *(const float4*)(msb + (d0 + lr) * TXn + lc);
            ass = *(const float4*)(ssb + (d0 + lr) * TXn + lc);
        }

        #pragma unroll
        for (int kk = 0; kk < 8; kk++) {
            unsigned long long a1[8], a2[8], b1[4], b2[4];
            {
                const ulonglong2* pa = (const ulonglong2*)&s_zd[kk][ty * 8];
                ulonglong2 t0 = pa[0], t1 = pa[1], t2 = pa[2], t3 = pa[3];
                a1[0]=t0.x; a1[1]=t0.y; a1[2]=t1.x; a1[3]=t1.y;
                a1[4]=t2.x; a1[5]=t2.y; a1[6]=t3.x; a1[7]=t3.y;
            }
            {
                const ulonglong2* pa = (const ulonglong2*)&s_z2[kk][ty * 8];
                ulonglong2 t0 = pa[0], t1 = pa[1], t2 = pa[2], t3 = pa[3];
                a2[0]=t0.x; a2[1]=t0.y; a2[2]=t1.x; a2[3]=t1.y;
                a2[4]=t2.x; a2[5]=t2.y; a2[6]=t3.x; a2[7]=t3.y;
            }
            {
                ulonglong2 lo = *(const ulonglong2*)&s_ms[kk][tx * 4];
                ulonglong2 hi = *(const ulonglong2*)&s_ms[kk][64 + tx * 4];
                b1[0]=lo.x; b1[1]=lo.y; b1[2]=hi.x; b1[3]=hi.y;
            }
            {
                ulonglong2 lo = *(const ulonglong2*)&s_s[kk][tx * 4];
                ulonglong2 hi = *(const ulonglong2*)&s_s[kk][64 + tx * 4];
                b2[0]=lo.x; b2[1]=lo.y; b2[2]=hi.x; b2[3]=hi.y;
            }
            #pragma unroll
            for (int i = 0; i < 8; i++)
                #pragma unroll
                for (int j = 0; j < 4; j++) {
                    fma2(acc[i][j], a1[i], b1[j]);
                    fma2(acc[i][j], a2[i], b2[j]);
                }
        }
    }

    float cv[8];
    *(float4*)&cv[0] = *(const float4*)(g_cvec + b * TXn + bx * 128 + tx * 8);
    *(float4*)&cv[4] = *(const float4*)(g_cvec + b * TXn + bx * 128 + tx * 8 + 4);

    float* outp = g_nc + (size_t)b * TYn * TXn + (size_t)(by * 128 + ty * 8) * TXn
                + bx * 128 + tx * 8;
    #pragma unroll
    for (int i = 0; i < 8; i++) {
        float2 f0 = *(float2*)&acc[i][0];
        float2 f1 = *(float2*)&acc[i][1];
        float2 f2 = *(float2*)&acc[i][2];
        float2 f3 = *(float2*)&acc[i][3];
        float4 o0 = make_float4(f0.x + cv[0], f0.y + cv[1], f1.x + cv[2], f1.y + cv[3]);
        float4 o1 = make_float4(f2.x + cv[4], f2.y + cv[5], f3.x + cv[6], f3.y + cv[7]);
        *(float4*)(outp + (size_t)i * TXn)     = o0;
        *(float4*)(outp + (size_t)i * TXn + 4) = o1;
    }
}

// ---------------------------------------------------------------------------
// Kernel 3: MAS — halo-parallel DP + cp.async chunk pipeline (unchanged core)
// ---------------------------------------------------------------------------
#define MAS_ROW_S(Y, TB)                                                     \
  {                                                                          \
    const float* rp = (TB) + ((Y) & 15) * TXn + ldoff;                       \
    float4 B0 = *(const float4*)rp;                                          \
    float4 B1 = *(const float4*)(rp + 4);                                    \
    float cur[8];                                                            \
    cur[0]=B0.x; cur[1]=B0.y; cur[2]=B0.z; cur[3]=B0.w;                      \
    cur[4]=B1.x; cur[5]=B1.y; cur[6]=B1.z; cur[7]=B1.w;                      \
    float lv = __shfl_up_sync(0xffffffffu, v[7], 1);                         \
    if (lane == 0) lv = NEGV;                                                \
    unsigned int bits = (lv > v[0]) ? 1u : 0u;                               \
    float nv0 = cur[0] + fmaxf(v[0], lv);                                    \
    _Pragma("unroll") for (int i = 7; i >= 1; i--) {                         \
      bits |= (v[i - 1] > v[i]) ? (1u << i) : 0u;                            \
      v[i] = cur[i] + fmaxf(v[i], v[i - 1]);                                 \
    }                                                                        \
    v[0] = nv0;                                                              \
    if ((Y) < TXn - 1) {                                                     \
      int ylim = (Y) - c0;                                                   \
      _Pragma("unroll") for (int i = 0; i < 8; i++)                          \
        if (i > ylim) v[i] = NEGV;                                           \
    }                                                                        \
    if (lane >= 16)                                                          \
      s_dirs[(Y) * 64 + w * 16 + (lane - 16)] = (unsigned char)bits;         \
  }

#define MAS_EXCH()                                                           \
  {                                                                          \
    if (lane >= 16) {                                                        \
      *(float4*)&s_exch[w * 128 + (lane - 16) * 8]                           \
          = make_float4(v[0], v[1], v[2], v[3]);                             \
      *(float4*)&s_exch[w * 128 + (lane - 16) * 8 + 4]                       \
          = make_float4(v[4], v[5], v[6], v[7]);                             \
    }                                                                        \
    __syncthreads();                                                         \
    if (w > 0 && lane < 16) {                                                \
      float4 e0 = *(const float4*)&s_exch[(w - 1) * 128 + lane * 8];         \
      float4 e1 = *(const float4*)&s_exch[(w - 1) * 128 + lane * 8 + 4];     \
      v[0]=e0.x; v[1]=e0.y; v[2]=e0.z; v[3]=e0.w;                            \
      v[4]=e1.x; v[5]=e1.y; v[6]=e1.z; v[7]=e1.w;                            \
    }                                                                        \
    __syncthreads();                                                         \
  }

#define LOAD_CHUNK(C, BUF)                                                   \
  {                                                                          \
    const float* src = nc + (size_t)(C) * 16 * TXn;                          \
    float* dstb = (BUF);                                                     \
    _Pragma("unroll") for (int i = 0; i < 16; i++)                           \
      cp16(dstb + (tid + i * 128) * 4, src + (tid + i * 128) * 4);           \
    CP_COMMIT();                                                             \
  }

__global__ __launch_bounds__(128) void mas_kernel(const float* __restrict__ logw,
                                                  float* __restrict__ out_llen,
                                                  float* __restrict__ out_attn) {
    extern __shared__ unsigned char s_dyn[];
    unsigned char* s_dirs = s_dyn;                       // 128 KB
    float* tileA = (float*)(s_dyn + TYn * 64);           // 32 KB
    float* tileB = tileA + 16 * TXn;                     // 32 KB
    __shared__ float s_exch[4 * 128];
    __shared__ unsigned short path_sm[TYn];
    __shared__ int w_sm[TXn];
    __shared__ float s_red[4];

    int b = blockIdx.x;
    int tid = threadIdx.x;
    int w = tid >> 5, lane = tid & 31;
    const float* nc = g_nc + (size_t)b * TYn * TXn;
    int cbase = (w - 1) * 128;
    int c0 = cbase + lane * 8;
    int ldoff = c0 < 0 ? 0 : c0;

    float v[8];
    #pragma unroll
    for (int i = 0; i < 8; i++) v[i] = NEGV;
    if (c0 == 0) v[0] = nc[0];

    LOAD_CHUNK(0, tileA);
    LOAD_CHUNK(1, tileB);

    int y = 1;
    for (int c = 0; c < TYn / 16; c++) {
        CP_WAIT1();
        __syncthreads();
        float* tb = (c & 1) ? tileB : tileA;
        int yend = c * 16 + 16;
        #pragma unroll 8
        for (; y < yend; y++) MAS_ROW_S(y, tb);
        __syncthreads();
        if (c + 2 < TYn / 16) LOAD_CHUNK(c + 2, tb);
        if ((c & 3) == 3 && c + 1 < TYn / 16) MAS_EXCH();
    }
    __syncthreads();

    if (tid == 0) {
        int idx = TXn - 1;
        for (int yy = TYn - 1; yy >= 1; yy--) {
            path_sm[yy] = (unsigned short)idx;
            idx -= (int)((s_dirs[yy * 64 + (idx >> 3)] >> (idx & 7)) & 1u);
        }
        path_sm[0] = (unsigned short)idx;
    }
    __syncthreads();

    for (int x = tid; x < TXn; x += 128) w_sm[x] = 0;
    __syncthreads();

    for (int yy = tid; yy < TYn; yy += 128) {
        int px = path_sm[yy];
        g_path[b * TYn + yy] = px;
        atomicAdd(&w_sm[px], 1);
        out_attn[(size_t)b * TYn * TXn + (size_t)yy * TXn + px] = 1.0f;
    }
    __syncthreads();

    float part = 0.0f;
    for (int x = tid; x < TXn; x += 128) {
        float lw = logw[b * TXn + x];
        float d  = lw - logf((float)w_sm[x] + 1e-6f);
        part += d * d;
    }
    #pragma unroll
    for (int o = 16; o > 0; o >>= 1)
        part += __shfl_down_sync(0xffffffffu, part, o);
    if (lane == 0) s_red[w] = part;
    __syncthreads();
    if (tid == 0) out_llen[b] = s_red[0] + s_red[1] + s_red[2] + s_red[3];
}

// ---------------------------------------------------------------------------
// Kernel 4: gather
// ---------------------------------------------------------------------------
__global__ void gather_kernel(const float* __restrict__ xm,
                              const float* __restrict__ xl,
                              float* __restrict__ out_main) {
    int b  = blockIdx.y;
    int dc = blockIdx.z;
    int y  = blockIdx.x * 256 + threadIdx.x;
    int px = g_path[b * TYn + y];
    const float* xmb = xm + b * Dn * TXn + px;
    const float* xlb = xl + b * Dn * TXn + px;
    float* o = out_main + (size_t)b * 2 * Dn * TYn + y;
    int d0 = dc * 24;
    #pragma unroll 4
    for (int d = d0; d < d0 + 24; d++)
        o[(size_t)d * TYn] = xmb[(size_t)d * TXn];
    #pragma unroll 4
    for (int d = d0; d < d0 + 24; d++)
        o[(size_t)(Dn + d) * TYn] = xlb[(size_t)d * TXn];
}

// ---------------------------------------------------------------------------
extern "C" void kernel_launch(void* const* d_in, const int* in_sizes, int n_in,
                              void* d_out, int out_size) {
    const float* xm   = (const float*)d_in[0];
    const float* xl   = (const float*)d_in[1];
    const float* z    = (const float*)d_in[2];
    const float* logw = (const float*)d_in[3];

    float* out       = (float*)d_out;
    const size_t OM  = (size_t)Bn * 2 * Dn * TYn;
    float* out_main  = out;
    float* out_llen  = out + OM;
    float* out_attn  = out + OM + Bn;

    cudaFuncSetAttribute(mas_kernel,
                         cudaFuncAttributeMaxDynamicSharedMemorySize,
                         TYn * 64 + 2 * 16 * TXn * (int)sizeof(float));

    // kernel order: prep(1) combine(2) gemm(3) mas(4 - captured) gather(5)
    prep_kernel<<<dim3(TXn / 128, Bn, 8), 128>>>(xm, xl);
    combine_kernel<<<(Bn * TXn) / 256, 256>>>();
    nc_gemm_kernel<<<dim3(TXn / 128, TYn / 128, Bn), 256>>>(z);
    cudaMemsetAsync(out_attn, 0, (size_t)Bn * TYn * TXn * sizeof(float));
    mas_kernel<<<Bn, 128, TYn * 64 + 2 * 16 * TXn * (int)sizeof(float)>>>(logw, out_llen, out_attn);
    gather_kernel<<<dim3(TYn / 256, Bn, 8), 256>>>(xm, xl, out_main);
}

// round 6
// speedup vs baseline: 3.3118x; 1.1021x over previous
#include <cuda_runtime.h>
#include <math.h>

#define Bn  16
#define Dn  192
#define TXn 512
#define TYn 2048
#define NEGV (-1e9f)

// ---- scratch (device globals; no allocation allowed) ----
__device__ __align__(16) float g_nc  [Bn * TYn * TXn];  // 64 MB neg_cent
__device__ __align__(16) float g_bms [Bn * Dn * TXn];
__device__ __align__(16) float g_bs  [Bn * Dn * TXn];
__device__ __align__(16) float g_cvec[Bn * TXn];
__device__ __align__(16) float g_cpart[8 * Bn * TXn];
__device__ int   g_path[Bn * TYn];

// packed fp32x2 FMA (Blackwell)
__device__ __forceinline__ void fma2(unsigned long long& d,
                                     unsigned long long a,
                                     unsigned long long b) {
    asm("fma.rn.f32x2 %0, %1, %2, %0;" : "+l"(d) : "l"(a), "l"(b));
}

__device__ __forceinline__ void cp16(float* dst_smem, const float* src) {
    unsigned int d = (unsigned int)__cvta_generic_to_shared(dst_smem);
    asm volatile("cp.async.cg.shared.global [%0], [%1], 16;" :: "r"(d), "l"(src));
}
#define CP_COMMIT() asm volatile("cp.async.commit_group;")
#define CP_WAIT1()  asm volatile("cp.async.wait_group 1;" ::: "memory")

// ---------------------------------------------------------------------------
// Kernel 1: prep — 8 D-chunks in parallel, deterministic partials
// ---------------------------------------------------------------------------
__global__ void prep_kernel(const float* __restrict__ xm,
                            const float* __restrict__ xl) {
    int b  = blockIdx.y;
    int dc = blockIdx.z;
    int x  = blockIdx.x * 128 + threadIdx.x;
    const float* xmb = xm + b * Dn * TXn;
    const float* xlb = xl + b * Dn * TXn;
    float* bms = g_bms + b * Dn * TXn;
    float* bs  = g_bs  + b * Dn * TXn;
    float c = 0.0f;
    int d0 = dc * 24;
    #pragma unroll 4
    for (int d = d0; d < d0 + 24; d++) {
        float m = xmb[d * TXn + x];
        float l = xlb[d * TXn + x];
        float s = expf(-2.0f * l);
        bs [d * TXn + x] = s;
        bms[d * TXn + x] = m * s;
        c += (-l) + (-0.5f * m * m * s);
    }
    g_cpart[dc * (Bn * TXn) + b * TXn + x] = c;
}

__global__ void combine_kernel() {
    int i = blockIdx.x * 256 + threadIdx.x;
    float c = -(float)Dn * 0.91893853320467274f;
    #pragma unroll
    for (int p = 0; p < 8; p++) c += g_cpart[p * (Bn * TXn) + i];
    g_cvec[i] = c;
}

// ---------------------------------------------------------------------------
// Kernel 2: nc GEMM, packed f32x2 FMAs, split-layout B (conflict-free)
// ---------------------------------------------------------------------------
__global__ __launch_bounds__(256) void nc_gemm_kernel(const float* __restrict__ z) {
    int bx = blockIdx.x;
    int by = blockIdx.y;
    int b  = blockIdx.z;
    if (bx > by) return;
    if (bx <= by - 13) return;

    __shared__ float2 s_zd[8][128];
    __shared__ float2 s_z2[8][128];
    __shared__ float  s_ms[8][128];
    __shared__ float  s_s [8][128];

    int tid = threadIdx.x;
    int lr = tid >> 5;
    int lc = (tid & 31) * 4;
    int ty = tid >> 4;
    int tx = tid & 15;
    int bsplit = ((lc >> 2) & 1) * 64 + (lc >> 3) * 4;

    const float* zb  = z     + b * Dn * TYn + by * 128;
    const float* msb = g_bms + b * Dn * TXn + bx * 128;
    const float* ssb = g_bs  + b * Dn * TXn + bx * 128;

    unsigned long long acc[8][4];
    #pragma unroll
    for (int i = 0; i < 8; i++)
        #pragma unroll
        for (int j = 0; j < 4; j++) acc[i][j] = 0ull;

    float4 az  = *(const float4*)(zb  + lr * TYn + lc);
    float4 ams = *(const float4*)(msb + lr * TXn + lc);
    float4 ass = *(const float4*)(ssb + lr * TXn + lc);

    for (int c = 0; c < Dn / 8; c++) {
        __syncthreads();
        {
            float4* pz = (float4*)&s_zd[lr][lc];
            pz[0] = make_float4(az.x, az.x, az.y, az.y);
            pz[1] = make_float4(az.z, az.z, az.w, az.w);
            float zx = -0.5f * az.x * az.x, zy = -0.5f * az.y * az.y;
            float zz = -0.5f * az.z * az.z, zw = -0.5f * az.w * az.w;
            float4* p2 = (float4*)&s_z2[lr][lc];
            p2[0] = make_float4(zx, zx, zy, zy);
            p2[1] = make_float4(zz, zz, zw, zw);
            *(float4*)&s_ms[lr][bsplit] = ams;
            *(float4*)&s_s [lr][bsplit] = ass;
        }
        __syncthreads();

        if (c + 1 < Dn / 8) {
            int d0 = (c + 1) * 8;
            az  = *(const float4*)(zb  + (d0 + lr) * TYn + lc);
            ams = *(const float4*)(msb + (d0 + lr) * TXn + lc);
            ass = *(const float4*)(ssb + (d0 + lr) * TXn + lc);
        }

        #pragma unroll
        for (int kk = 0; kk < 8; kk++) {
            unsigned long long a1[8], a2[8], b1[4], b2[4];
            {
                const ulonglong2* pa = (const ulonglong2*)&s_zd[kk][ty * 8];
                ulonglong2 t0 = pa[0], t1 = pa[1], t2 = pa[2], t3 = pa[3];
                a1[0]=t0.x; a1[1]=t0.y; a1[2]=t1.x; a1[3]=t1.y;
                a1[4]=t2.x; a1[5]=t2.y; a1[6]=t3.x; a1[7]=t3.y;
            }
            {
                const ulonglong2* pa = (const ulonglong2*)&s_z2[kk][ty * 8];
                ulonglong2 t0 = pa[0], t1 = pa[1], t2 = pa[2], t3 = pa[3];
                a2[0]=t0.x; a2[1]=t0.y; a2[2]=t1.x; a2[3]=t1.y;
                a2[4]=t2.x; a2[5]=t2.y; a2[6]=t3.x; a2[7]=t3.y;
            }
            {
                ulonglong2 lo = *(const ulonglong2*)&s_ms[kk][tx * 4];
                ulonglong2 hi = *(const ulonglong2*)&s_ms[kk][64 + tx * 4];
                b1[0]=lo.x; b1[1]=lo.y; b1[2]=hi.x; b1[3]=hi.y;
            }
            {
                ulonglong2 lo = *(const ulonglong2*)&s_s[kk][tx * 4];
                ulonglong2 hi = *(const ulonglong2*)&s_s[kk][64 + tx * 4];
                b2[0]=lo.x; b2[1]=lo.y; b2[2]=hi.x; b2[3]=hi.y;
            }
            #pragma unroll
            for (int i = 0; i < 8; i++)
                #pragma unroll
                for (int j = 0; j < 4; j++) {
                    fma2(acc[i][j], a1[i], b1[j]);
                    fma2(acc[i][j], a2[i], b2[j]);
                }
        }
    }

    float cv[8];
    *(float4*)&cv[0] = *(const float4*)(g_cvec + b * TXn + bx * 128 + tx * 8);
    *(float4*)&cv[4] = *(const float4*)(g_cvec + b * TXn + bx * 128 + tx * 8 + 4);

    float* outp = g_nc + (size_t)b * TYn * TXn + (size_t)(by * 128 + ty * 8) * TXn
                + bx * 128 + tx * 8;
    #pragma unroll
    for (int i = 0; i < 8; i++) {
        float2 f0 = *(float2*)&acc[i][0];
        float2 f1 = *(float2*)&acc[i][1];
        float2 f2 = *(float2*)&acc[i][2];
        float2 f3 = *(float2*)&acc[i][3];
        float4 o0 = make_float4(f0.x + cv[0], f0.y + cv[1], f1.x + cv[2], f1.y + cv[3]);
        float4 o1 = make_float4(f2.x + cv[4], f2.y + cv[5], f3.x + cv[6], f3.y + cv[7]);
        *(float4*)(outp + (size_t)i * TXn)     = o0;
        *(float4*)(outp + (size_t)i * TXn + 4) = o1;
    }
}

// ---------------------------------------------------------------------------
// Kernel 3: MAS — 8 warps/batch (2/SMSP), 4 cols/lane (64 own + 64 halo),
// ballot-based direction bits, cp.async double-buffered feed.
// ---------------------------------------------------------------------------
#define MAS_ROW8(Y, TB, MASKED)                                              \
  {                                                                          \
    float4 c4 = *(const float4*)((TB) + ((Y) & 15) * TXn + ldoff);           \
    float lv = __shfl_up_sync(0xffffffffu, v[3], 1);                         \
    if (lane == 0) lv = NEGV;                                                \
    unsigned int b0 = __ballot_sync(0xffffffffu, lv   > v[0]);               \
    unsigned int b1 = __ballot_sync(0xffffffffu, v[0] > v[1]);               \
    unsigned int b2 = __ballot_sync(0xffffffffu, v[1] > v[2]);               \
    unsigned int b3 = __ballot_sync(0xffffffffu, v[2] > v[3]);               \
    v[3] = c4.w + fmaxf(v[3], v[2]);                                         \
    v[2] = c4.z + fmaxf(v[2], v[1]);                                         \
    v[1] = c4.y + fmaxf(v[1], v[0]);                                         \
    v[0] = c4.x + fmaxf(v[0], lv);                                           \
    if (MASKED) {                                                            \
      int ylim = (Y) - c0;                                                   \
      if (0 > ylim) v[0] = NEGV;                                             \
      if (1 > ylim) v[1] = NEGV;                                             \
      if (2 > ylim) v[2] = NEGV;                                             \
      if (3 > ylim) v[3] = NEGV;                                             \
    }                                                                        \
    if (lane == 0) {                                                         \
      uint2 st;                                                              \
      st.x = (b0 >> 16) | (b1 & 0xFFFF0000u);                                \
      st.y = (b2 >> 16) | (b3 & 0xFFFF0000u);                                \
      *(uint2*)&s_dirs32[(Y) * 16 + w * 2] = st;                             \
    }                                                                        \
  }

#define MAS_EXCH8()                                                          \
  {                                                                          \
    if (lane >= 16)                                                          \
      *(float4*)&s_exch[w * 64 + (lane - 16) * 4]                            \
          = make_float4(v[0], v[1], v[2], v[3]);                             \
    __syncthreads();                                                         \
    if (w > 0 && lane < 16) {                                                \
      float4 e = *(const float4*)&s_exch[(w - 1) * 64 + lane * 4];           \
      v[0] = e.x; v[1] = e.y; v[2] = e.z; v[3] = e.w;                        \
    }                                                                        \
    __syncthreads();                                                         \
  }

#define LOAD_CHUNK8(C, BUF)                                                  \
  {                                                                          \
    const float* src = nc + (size_t)(C) * 16 * TXn;                          \
    float* dstb = (BUF);                                                     \
    _Pragma("unroll") for (int i = 0; i < 8; i++)                            \
      cp16(dstb + (tid + i * 256) * 4, src + (tid + i * 256) * 4);           \
    CP_COMMIT();                                                             \
  }

__global__ __launch_bounds__(256) void mas_kernel(const float* __restrict__ logw,
                                                  float* __restrict__ out_llen,
                                                  float* __restrict__ out_attn) {
    extern __shared__ unsigned char s_dyn[];
    unsigned int* s_dirs32 = (unsigned int*)s_dyn;       // 2048*16*4 = 128 KB
    float* tileA = (float*)(s_dyn + TYn * 64);           // 32 KB
    float* tileB = tileA + 16 * TXn;                     // 32 KB
    __shared__ float s_exch[8 * 64];
    __shared__ unsigned short path_sm[TYn];
    __shared__ int w_sm[TXn];
    __shared__ float s_red[8];

    int b = blockIdx.x;
    int tid = threadIdx.x;
    int w = tid >> 5, lane = tid & 31;
    const float* nc = g_nc + (size_t)b * TYn * TXn;
    int c0 = (w - 1) * 64 + lane * 4;          // negative in warp-0 halo
    int ldoff = c0 < 0 ? 0 : c0;

    float v[4];
    #pragma unroll
    for (int i = 0; i < 4; i++) v[i] = NEGV;
    if (c0 == 0) v[0] = nc[0];

    LOAD_CHUNK8(0, tileA);
    LOAD_CHUNK8(1, tileB);

    for (int c = 0; c < TYn / 16; c++) {
        CP_WAIT1();
        __syncthreads();
        float* tb = (c & 1) ? tileB : tileA;
        if (c == 0) {
            #pragma unroll
            for (int r = 1; r < 16; r++) MAS_ROW8(r, tb, 1);
        } else if (c < 32) {
            int ybase = c * 16;
            #pragma unroll
            for (int r = 0; r < 16; r++) MAS_ROW8(ybase + r, tb, 1);
        } else {
            int ybase = c * 16;
            #pragma unroll
            for (int r = 0; r < 16; r++) MAS_ROW8(ybase + r, tb, 0);
        }
        __syncthreads();
        if (c + 2 < TYn / 16) LOAD_CHUNK8(c + 2, tb);
        if ((c & 3) == 3 && c + 1 < TYn / 16) MAS_EXCH8();
    }
    __syncthreads();

    // serial backtrack: col c -> warp c>>6, i=c&3, word pair i>>1,
    // bitpos = ((i&1)<<4) + ((c>>2)&15)
    if (tid == 0) {
        int idx = TXn - 1;
        for (int yy = TYn - 1; yy >= 1; yy--) {
            path_sm[yy] = (unsigned short)idx;
            int i = idx & 3;
            unsigned int word = s_dirs32[yy * 16 + (idx >> 6) * 2 + (i >> 1)];
            int bitpos = ((i & 1) << 4) + ((idx >> 2) & 15);
            idx -= (int)((word >> bitpos) & 1u);
        }
        path_sm[0] = (unsigned short)idx;
    }
    __syncthreads();

    for (int x = tid; x < TXn; x += 256) w_sm[x] = 0;
    __syncthreads();

    for (int yy = tid; yy < TYn; yy += 256) {
        int px = path_sm[yy];
        g_path[b * TYn + yy] = px;
        atomicAdd(&w_sm[px], 1);
        out_attn[(size_t)b * TYn * TXn + (size_t)yy * TXn + px] = 1.0f;
    }
    __syncthreads();

    float part = 0.0f;
    for (int x = tid; x < TXn; x += 256) {
        float lw = logw[b * TXn + x];
        float d  = lw - logf((float)w_sm[x] + 1e-6f);
        part += d * d;
    }
    #pragma unroll
    for (int o = 16; o > 0; o >>= 1)
        part += __shfl_down_sync(0xffffffffu, part, o);
    if (lane == 0) s_red[w] = part;
    __syncthreads();
    if (tid == 0) {
        float s = 0.0f;
        #pragma unroll
        for (int i = 0; i < 8; i++) s += s_red[i];
        out_llen[b] = s;
    }
}

// ---------------------------------------------------------------------------
// Kernel 4: gather
// ---------------------------------------------------------------------------
__global__ void gather_kernel(const float* __restrict__ xm,
                              const float* __restrict__ xl,
                              float* __restrict__ out_main) {
    int b  = blockIdx.y;
    int dc = blockIdx.z;
    int y  = blockIdx.x * 256 + threadIdx.x;
    int px = g_path[b * TYn + y];
    const float* xmb = xm + b * Dn * TXn + px;
    const float* xlb = xl + b * Dn * TXn + px;
    float* o = out_main + (size_t)b * 2 * Dn * TYn + y;
    int d0 = dc * 24;
    #pragma unroll 4
    for (int d = d0; d < d0 + 24; d++)
        o[(size_t)d * TYn] = xmb[(size_t)d * TXn];
    #pragma unroll 4
    for (int d = d0; d < d0 + 24; d++)
        o[(size_t)(Dn + d) * TYn] = xlb[(size_t)d * TXn];
}

// ---------------------------------------------------------------------------
extern "C" void kernel_launch(void* const* d_in, const int* in_sizes, int n_in,
                              void* d_out, int out_size) {
    const float* xm   = (const float*)d_in[0];
    const float* xl   = (const float*)d_in[1];
    const float* z    = (const float*)d_in[2];
    const float* logw = (const float*)d_in[3];

    float* out       = (float*)d_out;
    const size_t OM  = (size_t)Bn * 2 * Dn * TYn;
    float* out_main  = out;
    float* out_llen  = out + OM;
    float* out_attn  = out + OM + Bn;

    int mas_smem = TYn * 64 + 2 * 16 * TXn * (int)sizeof(float);
    cudaFuncSetAttribute(mas_kernel,
                         cudaFuncAttributeMaxDynamicSharedMemorySize, mas_smem);

    // kernel order: prep(1) combine(2) gemm(3) mas(4 - captured) gather(5)
    prep_kernel<<<dim3(TXn / 128, Bn, 8), 128>>>(xm, xl);
    combine_kernel<<<(Bn * TXn) / 256, 256>>>();
    nc_gemm_kernel<<<dim3(TXn / 128, TYn / 128, Bn), 256>>>(z);
    cudaMemsetAsync(out_attn, 0, (size_t)Bn * TYn * TXn * sizeof(float));
    mas_kernel<<<Bn, 256, mas_smem>>>(logw, out_llen, out_attn);
    gather_kernel<<<dim3(TYn / 256, Bn, 8), 256>>>(xm, xl, out_main);
}

// round 7
// speedup vs baseline: 3.4217x; 1.0332x over previous
#include <cuda_runtime.h>
#include <math.h>

#define Bn  16
#define Dn  192
#define TXn 512
#define TYn 2048
#define NEGV (-1e9f)

// ---- scratch (device globals; no allocation allowed) ----
__device__ __align__(16) float g_nc  [Bn * TYn * TXn];  // 64 MB neg_cent
__device__ __align__(16) float g_bms [Bn * Dn * TXn];
__device__ __align__(16) float g_bs  [Bn * Dn * TXn];
__device__ __align__(16) float g_cvec[Bn * TXn];
__device__ __align__(16) float g_cpart[8 * Bn * TXn];
__device__ int   g_path[Bn * TYn];

// packed fp32x2 FMA (Blackwell)
__device__ __forceinline__ void fma2(unsigned long long& d,
                                     unsigned long long a,
                                     unsigned long long b) {
    asm("fma.rn.f32x2 %0, %1, %2, %0;" : "+l"(d) : "l"(a), "l"(b));
}

__device__ __forceinline__ void cp16(float* dst_smem, const float* src) {
    unsigned int d = (unsigned int)__cvta_generic_to_shared(dst_smem);
    asm volatile("cp.async.cg.shared.global [%0], [%1], 16;" :: "r"(d), "l"(src));
}
#define CP_COMMIT() asm volatile("cp.async.commit_group;")
#define CP_WAIT1()  asm volatile("cp.async.wait_group 1;" ::: "memory")

// ---------------------------------------------------------------------------
// Kernel 1: prep — 8 D-chunks in parallel, deterministic partials
// ---------------------------------------------------------------------------
__global__ void prep_kernel(const float* __restrict__ xm,
                            const float* __restrict__ xl) {
    int b  = blockIdx.y;
    int dc = blockIdx.z;
    int x  = blockIdx.x * 128 + threadIdx.x;
    const float* xmb = xm + b * Dn * TXn;
    const float* xlb = xl + b * Dn * TXn;
    float* bms = g_bms + b * Dn * TXn;
    float* bs  = g_bs  + b * Dn * TXn;
    float c = 0.0f;
    int d0 = dc * 24;
    #pragma unroll 4
    for (int d = d0; d < d0 + 24; d++) {
        float m = xmb[d * TXn + x];
        float l = xlb[d * TXn + x];
        float s = expf(-2.0f * l);
        bs [d * TXn + x] = s;
        bms[d * TXn + x] = m * s;
        c += (-l) + (-0.5f * m * m * s);
    }
    g_cpart[dc * (Bn * TXn) + b * TXn + x] = c;
}

__global__ void combine_kernel() {
    int i = blockIdx.x * 256 + threadIdx.x;
    float c = -(float)Dn * 0.91893853320467274f;
    #pragma unroll
    for (int p = 0; p < 8; p++) c += g_cpart[p * (Bn * TXn) + i];
    g_cvec[i] = c;
}

// ---------------------------------------------------------------------------
// Kernel 2: nc GEMM, packed f32x2 FMAs, split-layout B (conflict-free)
// ---------------------------------------------------------------------------
__global__ __launch_bounds__(256) void nc_gemm_kernel(const float* __restrict__ z) {
    int bx = blockIdx.x;
    int by = blockIdx.y;
    int b  = blockIdx.z;
    if (bx > by) return;
    if (bx <= by - 13) return;

    __shared__ float2 s_zd[8][128];
    __shared__ float2 s_z2[8][128];
    __shared__ float  s_ms[8][128];
    __shared__ float  s_s [8][128];

    int tid = threadIdx.x;
    int lr = tid >> 5;
    int lc = (tid & 31) * 4;
    int ty = tid >> 4;
    int tx = tid & 15;
    int bsplit = ((lc >> 2) & 1) * 64 + (lc >> 3) * 4;

    const float* zb  = z     + b * Dn * TYn + by * 128;
    const float* msb = g_bms + b * Dn * TXn + bx * 128;
    const float* ssb = g_bs  + b * Dn * TXn + bx * 128;

    unsigned long long acc[8][4];
    #pragma unroll
    for (int i = 0; i < 8; i++)
        #pragma unroll
        for (int j = 0; j < 4; j++) acc[i][j] = 0ull;

    float4 az  = *(const float4*)(zb  + lr * TYn + lc);
    float4 ams = *(const float4*)(msb + lr * TXn + lc);
    float4 ass = *(const float4*)(ssb + lr * TXn + lc);

    for (int c = 0; c < Dn / 8; c++) {
        __syncthreads();
        {
            float4* pz = (float4*)&s_zd[lr][lc];
            pz[0] = make_float4(az.x, az.x, az.y, az.y);
            pz[1] = make_float4(az.z, az.z, az.w, az.w);
            float zx = -0.5f * az.x * az.x, zy = -0.5f * az.y * az.y;
            float zz = -0.5f * az.z * az.z, zw = -0.5f * az.w * az.w;
            float4* p2 = (float4*)&s_z2[lr][lc];
            p2[0] = make_float4(zx, zx, zy, zy);
            p2[1] = make_float4(zz, zz, zw, zw);
            *(float4*)&s_ms[lr][bsplit] = ams;
            *(float4*)&s_s [lr][bsplit] = ass;
        }
        __syncthreads();

        if (c + 1 < Dn / 8) {
            int d0 = (c + 1) * 8;
            az  = *(const float4*)(zb  + (d0 + lr) * TYn + lc);
            ams = *(const float4*)(msb + (d0 + lr) * TXn + lc);
            ass = *(const float4*)(ssb + (d0 + lr) * TXn + lc);
        }

        #pragma unroll
        for (int kk = 0; kk < 8; kk++) {
            unsigned long long a1[8], a2[8], b1[4], b2[4];
            {
                const ulonglong2* pa = (const ulonglong2*)&s_zd[kk][ty * 8];
                ulonglong2 t0 = pa[0], t1 = pa[1], t2 = pa[2], t3 = pa[3];
                a1[0]=t0.x; a1[1]=t0.y; a1[2]=t1.x; a1[3]=t1.y;
                a1[4]=t2.x; a1[5]=t2.y; a1[6]=t3.x; a1[7]=t3.y;
            }
            {
                const ulonglong2* pa = (const ulonglong2*)&s_z2[kk][ty * 8];
                ulonglong2 t0 = pa[0], t1 = pa[1], t2 = pa[2], t3 = pa[3];
                a2[0]=t0.x; a2[1]=t0.y; a2[2]=t1.x; a2[3]=t1.y;
                a2[4]=t2.x; a2[5]=t2.y; a2[6]=t3.x; a2[7]=t3.y;
            }
            {
                ulonglong2 lo = *(const ulonglong2*)&s_ms[kk][tx * 4];
                ulonglong2 hi = *(const ulonglong2*)&s_ms[kk][64 + tx * 4];
                b1[0]=lo.x; b1[1]=lo.y; b1[2]=hi.x; b1[3]=hi.y;
            }
            {
                ulonglong2 lo = *(const ulonglong2*)&s_s[kk][tx * 4];
                ulonglong2 hi = *(const ulonglong2*)&s_s[kk][64 + tx * 4];
                b2[0]=lo.x; b2[1]=lo.y; b2[2]=hi.x; b2[3]=hi.y;
            }
            #pragma unroll
            for (int i = 0; i < 8; i++)
                #pragma unroll
                for (int j = 0; j < 4; j++) {
                    fma2(acc[i][j], a1[i], b1[j]);
                    fma2(acc[i][j], a2[i], b2[j]);
                }
        }
    }

    float cv[8];
    *(float4*)&cv[0] = *(const float4*)(g_cvec + b * TXn + bx * 128 + tx * 8);
    *(float4*)&cv[4] = *(const float4*)(g_cvec + b * TXn + bx * 128 + tx * 8 + 4);

    float* outp = g_nc + (size_t)b * TYn * TXn + (size_t)(by * 128 + ty * 8) * TXn
                + bx * 128 + tx * 8;
    #pragma unroll
    for (int i = 0; i < 8; i++) {
        float2 f0 = *(float2*)&acc[i][0];
        float2 f1 = *(float2*)&acc[i][1];
        float2 f2 = *(float2*)&acc[i][2];
        float2 f3 = *(float2*)&acc[i][3];
        float4 o0 = make_float4(f0.x + cv[0], f0.y + cv[1], f1.x + cv[2], f1.y + cv[3]);
        float4 o1 = make_float4(f2.x + cv[4], f2.y + cv[5], f3.x + cv[6], f3.y + cv[7]);
        *(float4*)(outp + (size_t)i * TXn)     = o0;
        *(float4*)(outp + (size_t)i * TXn + 4) = o1;
    }
}

// ---------------------------------------------------------------------------
// Kernel 3: MAS — 8 warps/batch, 4 cols/lane, NO ballots: direction bits
// accumulate in a register (4 bits/row), own-lanes store 1 word per 8 rows.
// ---------------------------------------------------------------------------
#define MAS_ROW8(Y, TB, MASKED)                                              \
  {                                                                          \
    float4 c4 = *(const float4*)((TB) + ((Y) & 15) * TXn + ldoff);           \
    float lv = __shfl_up_sync(0xffffffffu, v[3], 1);                         \
    if (lane == 0) lv = NEGV;                                                \
    unsigned int bb = (lv   > v[0] ? 1u : 0u) | (v[0] > v[1] ? 2u : 0u)      \
                    | (v[1] > v[2] ? 4u : 0u) | (v[2] > v[3] ? 8u : 0u);     \
    bits_acc |= bb << (((Y) & 7) * 4);                                       \
    v[3] = c4.w + fmaxf(v[3], v[2]);                                         \
    v[2] = c4.z + fmaxf(v[2], v[1]);                                         \
    v[1] = c4.y + fmaxf(v[1], v[0]);                                         \
    v[0] = c4.x + fmaxf(v[0], lv);                                           \
    if (MASKED) {                                                            \
      int ylim = (Y) - c0;                                                   \
      if (0 > ylim) v[0] = NEGV;                                             \
      if (1 > ylim) v[1] = NEGV;                                             \
      if (2 > ylim) v[2] = NEGV;                                             \
      if (3 > ylim) v[3] = NEGV;                                             \
    }                                                                        \
    if (((Y) & 7) == 7) {                                                    \
      if (lane >= 16)                                                        \
        s_dirs32[((Y) >> 3) * 128 + w * 16 + (lane - 16)] = bits_acc;        \
      bits_acc = 0u;                                                         \
    }                                                                        \
  }

#define MAS_EXCH8()                                                          \
  {                                                                          \
    if (lane >= 16)                                                          \
      *(float4*)&s_exch[w * 64 + (lane - 16) * 4]                            \
          = make_float4(v[0], v[1], v[2], v[3]);                             \
    __syncthreads();                                                         \
    if (w > 0 && lane < 16) {                                                \
      float4 e = *(const float4*)&s_exch[(w - 1) * 64 + lane * 4];           \
      v[0] = e.x; v[1] = e.y; v[2] = e.z; v[3] = e.w;                        \
    }                                                                        \
    __syncthreads();                                                         \
  }

#define LOAD_CHUNK8(C, BUF)                                                  \
  {                                                                          \
    const float* src = nc + (size_t)(C) * 16 * TXn;                          \
    float* dstb = (BUF);                                                     \
    _Pragma("unroll") for (int i = 0; i < 8; i++)                            \
      cp16(dstb + (tid + i * 256) * 4, src + (tid + i * 256) * 4);           \
    CP_COMMIT();                                                             \
  }

__global__ __launch_bounds__(256) void mas_kernel(const float* __restrict__ logw,
                                                  float* __restrict__ out_llen,
                                                  float* __restrict__ out_attn) {
    extern __shared__ unsigned char s_dyn[];
    unsigned int* s_dirs32 = (unsigned int*)s_dyn;       // 256*128*4 = 128 KB
    float* tileA = (float*)(s_dyn + TYn * 64);           // 32 KB
    float* tileB = tileA + 16 * TXn;                     // 32 KB
    __shared__ float s_exch[8 * 64];
    __shared__ unsigned short path_sm[TYn];
    __shared__ int w_sm[TXn];
    __shared__ float s_red[8];

    int b = blockIdx.x;
    int tid = threadIdx.x;
    int w = tid >> 5, lane = tid & 31;
    const float* nc = g_nc + (size_t)b * TYn * TXn;
    int c0 = (w - 1) * 64 + lane * 4;          // negative in warp-0 halo
    int ldoff = c0 < 0 ? 0 : c0;

    float v[4];
    #pragma unroll
    for (int i = 0; i < 4; i++) v[i] = NEGV;
    if (c0 == 0) v[0] = nc[0];
    unsigned int bits_acc = 0u;

    LOAD_CHUNK8(0, tileA);
    LOAD_CHUNK8(1, tileB);

    for (int c = 0; c < TYn / 16; c++) {
        CP_WAIT1();
        __syncthreads();
        float* tb = (c & 1) ? tileB : tileA;
        if (c == 0) {
            #pragma unroll
            for (int r = 1; r < 16; r++) MAS_ROW8(r, tb, 1);
        } else if (c < 32) {
            int ybase = c * 16;
            #pragma unroll
            for (int r = 0; r < 16; r++) MAS_ROW8(ybase + r, tb, 1);
        } else {
            int ybase = c * 16;
            #pragma unroll
            for (int r = 0; r < 16; r++) MAS_ROW8(ybase + r, tb, 0);
        }
        __syncthreads();
        if (c + 2 < TYn / 16) LOAD_CHUNK8(c + 2, tb);
        if ((c & 3) == 3 && c + 1 < TYn / 16) MAS_EXCH8();
    }
    __syncthreads();

    // serial backtrack: col c -> word [(y>>3)*128 + (c>>6)*16 + ((c>>2)&15)],
    // bit (y&7)*4 + (c&3)
    if (tid == 0) {
        int idx = TXn - 1;
        for (int yy = TYn - 1; yy >= 1; yy--) {
            path_sm[yy] = (unsigned short)idx;
            unsigned int word =
                s_dirs32[(yy >> 3) * 128 + (idx >> 6) * 16 + ((idx >> 2) & 15)];
            int bitpos = ((yy & 7) << 2) + (idx & 3);
            idx -= (int)((word >> bitpos) & 1u);
        }
        path_sm[0] = (unsigned short)idx;
    }
    __syncthreads();

    for (int x = tid; x < TXn; x += 256) w_sm[x] = 0;
    __syncthreads();

    for (int yy = tid; yy < TYn; yy += 256) {
        int px = path_sm[yy];
        g_path[b * TYn + yy] = px;
        atomicAdd(&w_sm[px], 1);
        out_attn[(size_t)b * TYn * TXn + (size_t)yy * TXn + px] = 1.0f;
    }
    __syncthreads();

    float part = 0.0f;
    for (int x = tid; x < TXn; x += 256) {
        float lw = logw[b * TXn + x];
        float d  = lw - logf((float)w_sm[x] + 1e-6f);
        part += d * d;
    }
    #pragma unroll
    for (int o = 16; o > 0; o >>= 1)
        part += __shfl_down_sync(0xffffffffu, part, o);
    if (lane == 0) s_red[w] = part;
    __syncthreads();
    if (tid == 0) {
        float s = 0.0f;
        #pragma unroll
        for (int i = 0; i < 8; i++) s += s_red[i];
        out_llen[b] = s;
    }
}

// ---------------------------------------------------------------------------
// Kernel 4: gather
// ---------------------------------------------------------------------------
__global__ void gather_kernel(const float* __restrict__ xm,
                              const float* __restrict__ xl,
                              float* __restrict__ out_main) {
    int b  = blockIdx.y;
    int dc = blockIdx.z;
    int y  = blockIdx.x * 256 + threadIdx.x;
    int px = g_path[b * TYn + y];
    const float* xmb = xm + b * Dn * TXn + px;
    const float* xlb = xl + b * Dn * TXn + px;
    float* o = out_main + (size_t)b * 2 * Dn * TYn + y;
    int d0 = dc * 24;
    #pragma unroll 4
    for (int d = d0; d < d0 + 24; d++)
        o[(size_t)d * TYn] = xmb[(size_t)d * TXn];
    #pragma unroll 4
    for (int d = d0; d < d0 + 24; d++)
        o[(size_t)(Dn + d) * TYn] = xlb[(size_t)d * TXn];
}

// ---------------------------------------------------------------------------
extern "C" void kernel_launch(void* const* d_in, const int* in_sizes, int n_in,
                              void* d_out, int out_size) {
    const float* xm   = (const float*)d_in[0];
    const float* xl   = (const float*)d_in[1];
    const float* z    = (const float*)d_in[2];
    const float* logw = (const float*)d_in[3];

    float* out       = (float*)d_out;
    const size_t OM  = (size_t)Bn * 2 * Dn * TYn;
    float* out_main  = out;
    float* out_llen  = out + OM;
    float* out_attn  = out + OM + Bn;

    int mas_smem = TYn * 64 + 2 * 16 * TXn * (int)sizeof(float);
    cudaFuncSetAttribute(mas_kernel,
                         cudaFuncAttributeMaxDynamicSharedMemorySize, mas_smem);

    // kernel order: prep(1) combine(2) gemm(3) mas(4 - captured) gather(5)
    prep_kernel<<<dim3(TXn / 128, Bn, 8), 128>>>(xm, xl);
    combine_kernel<<<(Bn * TXn) / 256, 256>>>();
    nc_gemm_kernel<<<dim3(TXn / 128, TYn / 128, Bn), 256>>>(z);
    cudaMemsetAsync(out_attn, 0, (size_t)Bn * TYn * TXn * sizeof(float));
    mas_kernel<<<Bn, 256, mas_smem>>>(logw, out_llen, out_attn);
    gather_kernel<<<dim3(TYn / 256, Bn, 8), 256>>>(xm, xl, out_main);
}